// round 5
// baseline (speedup 1.0000x reference)
#include <cuda_runtime.h>
#include <cstdint>

#define LDW 6144
#define NEGBIT 0x80000000u

// scratch (device globals; allocation in kernel_launch forbidden)
__device__ float g_PreR[1024 * 4096];
__device__ float g_PreI[1024 * 4096];
__device__ float g_XhR [1024 * 2048];
__device__ float g_XhI [1024 * 2048];
__device__ float g_HhR [1024 * 2048];
__device__ float g_HhI [1024 * 2048];
__device__ float g_RH  [1024 * 4096];
__device__ float g_Xr  [1024 * 4096];   // tf32-rounded inputs
__device__ float g_Hr  [1024 * 4096];   // tf32-rounded h_tm1

__device__ __forceinline__ unsigned f2tf(float x) {
    unsigned u; asm("cvt.rna.tf32.f32 %0, %1;" : "=r"(u) : "f"(x)); return u;
}
__device__ __forceinline__ float f2tff(float x) {
    unsigned u = f2tf(x); return __uint_as_float(u);
}
__device__ __forceinline__ uint32_t s2u(const void* p) {
    uint32_t a;
    asm("{ .reg .u64 t; cvta.to.shared.u64 t, %1; cvt.u32.u64 %0, t; }" : "=r"(a) : "l"(p));
    return a;
}

#define CP_ASYNC16(dst, src) \
    asm volatile("cp.async.cg.shared.global [%0], [%1], 16;" :: "r"(dst), "l"(src))
#define CP_COMMIT() asm volatile("cp.async.commit_group;" ::: "memory")
#define CP_WAIT0()  asm volatile("cp.async.wait_group 0;" ::: "memory")

// SW128 swizzle on byte offset within a tile of 128B rows
#define SW(o) ((o) ^ (((o) >> 3) & 0x70))

#define LDSM4(r, a) \
    asm volatile("ldmatrix.sync.aligned.m8n8.x4.shared.b16 {%0,%1,%2,%3}, [%4];" \
        : "=r"((r)[0]), "=r"((r)[1]), "=r"((r)[2]), "=r"((r)[3]) : "r"(a))

#define MMA(acc, a, b0, b1) \
    asm volatile("mma.sync.aligned.m16n8k8.row.col.f32.tf32.tf32.f32 " \
        "{%0,%1,%2,%3},{%4,%5,%6,%7},{%8,%9},{%0,%1,%2,%3};" \
        : "+f"((acc)[0]), "+f"((acc)[1]), "+f"((acc)[2]), "+f"((acc)[3]) \
        : "r"((a)[0]), "r"((a)[1]), "r"((a)[2]), "r"((a)[3]), "r"(b0), "r"(b1))

// smem: 2 stages x (A 16KB + B 16KB)
#define STAGE    32768
#define SM_B_OFF 16384
#define SMEM_TOTAL (2 * STAGE)

// ---------------------------------------------------------------------------
// tf32 GEMM: C[1024 x N] = A[1024 x K] @ Wsel (+bias)
// A is pre-rounded to tf32 (cp.async straight to smem).
// K in 2048-row segments; seg -> weight + sign by variant v (real/imag):
//   v=0: half0 -> W1 (+), half1 -> W2 (+)
//   v=1: half0 -> W2 (-), half1 -> W1 (+)
// blk = seg>>1 picks (W1a,W2a) vs (W1b,W2b). A rows k<4096 from A0 else A1.
// 128 threads = 4 warps, warp tile 64x64. grid: x = m-tile, y = n-tile*2 + v.
// ---------------------------------------------------------------------------
__global__ void __launch_bounds__(128, 2) gemm_tf32(
    const float* __restrict__ A0, const float* __restrict__ A1,
    const float* __restrict__ W1a, const float* __restrict__ W2a,
    const float* __restrict__ W1b, const float* __restrict__ W2b,
    int wcol0, int KT,
    const float* __restrict__ biasR, const float* __restrict__ biasI,
    float* __restrict__ CR, float* __restrict__ CI, int ldC)
{
    extern __shared__ char smem[];
    const uint32_t sb = s2u(smem);

    const int tid  = threadIdx.x;
    const int lane = tid & 31;
    const int warp = tid >> 5;
    const int wm   = warp >> 1;   // 0..1
    const int wn   = warp & 1;    // 0..1
    const int bm   = blockIdx.x;
    const int bn   = blockIdx.y >> 1;
    const int v    = blockIdx.y & 1;

    const float* bias = v ? biasI : biasR;
    float* C = v ? CI : CR;

    float acc[4][8][4];
    #pragma unroll
    for (int i = 0; i < 4; i++)
        #pragma unroll
        for (int j = 0; j < 8; j++)
            #pragma unroll
            for (int k = 0; k < 4; k++) acc[i][j][k] = 0.f;

    // ---- producer coords ----
    const int bn2 = tid & 31;          // B n group (4 cols)
    const int bk2 = tid >> 5;          // B k block (8 rows)
    const size_t mBase = (size_t)(bm * 128);
    const int    gn    = wcol0 + bn * 128;

    // ---- consumer (ldmatrix) constants ----
    const uint32_t xorv = (lane & 7) * 16;
    const uint32_t l87  = ((lane >> 3) & 1) * 8 + (lane & 7);
    const uint32_t p16  = (lane >> 4) * 16;
    const uint32_t aRow = (wm * 64 + l87) * 128;
    const uint32_t bRow = (wn * 64 + (lane & 7)) * 128;
    uint32_t aoff[4], boff[2];
    #pragma unroll
    for (int s = 0; s < 4; s++)  aoff[s]  = (s * 32 + p16) ^ xorv;
    #pragma unroll
    for (int sp = 0; sp < 2; sp++) boff[sp] = (sp * 64 + (lane >> 3) * 16) ^ xorv;

    float4 bv[8];
    unsigned nextSgn = 0;

    // A tile via cp.async: thread = row, 8 chunks of 16B
#define CP_A(KT_IDX, SDST)                                                          \
    do {                                                                            \
        const int kg = (KT_IDX) * 32;                                               \
        const float* Ap = (kg >= 4096) ? A1 : A0;                                   \
        const float* asrc = Ap + (mBase + tid) * 4096 + (kg & 4095);                \
        const uint32_t ad = (SDST);                                                 \
        _Pragma("unroll")                                                           \
        for (int c = 0; c < 8; c++)                                                 \
            CP_ASYNC16(ad + SW(tid * 128 + c * 16), asrc + c * 4);                  \
        CP_COMMIT();                                                                \
    } while (0)

    // B tile LDG: 8 float4 (8 k-rows x 4 n-cols), routing + sign -> nextSgn
#define LDG_B(KT_IDX)                                                               \
    do {                                                                            \
        const int kg = (KT_IDX) * 32;                                               \
        const int seg = kg >> 11, blk = seg >> 1, half = seg & 1;                   \
        const float* W1 = blk ? W1b : W1a;                                          \
        const float* W2 = blk ? W2b : W2a;                                          \
        const float* Wp;                                                            \
        if (v == 0) { Wp = half ? W2 : W1; nextSgn = 0u; }                          \
        else        { Wp = half ? W1 : W2; nextSgn = half ? 0u : NEGBIT; }          \
        const float* bbase = Wp + (size_t)((kg & 2047) + bk2 * 8) * LDW + gn + bn2 * 4; \
        _Pragma("unroll")                                                           \
        for (int kk = 0; kk < 8; kk++)                                              \
            bv[kk] = *(const float4*)(bbase + (size_t)kk * LDW);                    \
    } while (0)

    // B transpose + cvt + sign + STS (n-major rows); applies nextSgn, which the
    // immediately-preceding LDG_B set for THIS tile (no intervening LDG_B).
#define STS_B(SDST)                                                                 \
    do {                                                                            \
        char* bstg = smem + ((SDST) - sb);                                          \
        const unsigned sgn = nextSgn;                                               \
        _Pragma("unroll")                                                           \
        for (int nn = 0; nn < 4; nn++) {                                            \
            uint4 t0, t1;                                                           \
            const float* f = (const float*)bv;                                      \
            t0.x = f2tf(f[0 * 4 + nn]) ^ sgn;                                       \
            t0.y = f2tf(f[1 * 4 + nn]) ^ sgn;                                       \
            t0.z = f2tf(f[2 * 4 + nn]) ^ sgn;                                       \
            t0.w = f2tf(f[3 * 4 + nn]) ^ sgn;                                       \
            t1.x = f2tf(f[4 * 4 + nn]) ^ sgn;                                       \
            t1.y = f2tf(f[5 * 4 + nn]) ^ sgn;                                       \
            t1.z = f2tf(f[6 * 4 + nn]) ^ sgn;                                       \
            t1.w = f2tf(f[7 * 4 + nn]) ^ sgn;                                       \
            *(uint4*)(bstg + SW((bn2 * 4 + nn) * 128 + bk2 * 32))      = t0;        \
            *(uint4*)(bstg + SW((bn2 * 4 + nn) * 128 + bk2 * 32 + 16)) = t1;        \
        }                                                                           \
    } while (0)

    // ---- prologue: fill stage 0 ----
    CP_A(0, sb);                          // A of stage 0
    LDG_B(0);
    CP_WAIT0();
    STS_B(sb + SM_B_OFF);                 // B of stage 0 (sign of tile 0)
    __syncthreads();

    for (int kt = 0; kt < KT; ++kt) {
        const uint32_t sA = sb + (kt & 1) * STAGE;
        const uint32_t sB = sA + SM_B_OFF;
        const int nstage = (kt + 1) & 1;

        if (kt + 1 < KT) {
            CP_A(kt + 1, sb + nstage * STAGE);
            LDG_B(kt + 1);
        }

        // ---- compute stage kt&1 ----
        #pragma unroll
        for (int sp = 0; sp < 2; sp++) {
            uint32_t bfr[8][4];
            #pragma unroll
            for (int nf = 0; nf < 8; nf++)
                LDSM4(bfr[nf], sB + bRow + nf * (8 * 128) + boff[sp]);
            #pragma unroll
            for (int sh = 0; sh < 2; sh++) {
                const int s = sp * 2 + sh;
                uint32_t afr[4][4];
                #pragma unroll
                for (int mf = 0; mf < 4; mf++)
                    LDSM4(afr[mf], sA + aRow + mf * (16 * 128) + aoff[s]);
                #pragma unroll
                for (int mf = 0; mf < 4; mf++)
                    #pragma unroll
                    for (int nf = 0; nf < 8; nf++)
                        MMA(acc[mf][nf], afr[mf], bfr[nf][2 * sh], bfr[nf][2 * sh + 1]);
            }
        }

        if (kt + 1 < KT) {
            STS_B(sb + nstage * STAGE + SM_B_OFF);   // sign of tile kt+1
            CP_WAIT0();
            __syncthreads();
        }
    }

    // ---- epilogue ----
    const int gid = lane >> 2;
    const int tig = lane & 3;
    #pragma unroll
    for (int mf = 0; mf < 4; mf++) {
        const int row = bm * 128 + wm * 64 + mf * 16 + gid;
        #pragma unroll
        for (int nf = 0; nf < 8; nf++) {
            const int col = bn * 128 + wn * 64 + nf * 8 + tig * 2;
            float bb0 = 0.f, bb1 = 0.f;
            if (bias) { bb0 = bias[col]; bb1 = bias[col + 1]; }
            float2 v0 = make_float2(acc[mf][nf][0] + bb0, acc[mf][nf][1] + bb1);
            float2 v1 = make_float2(acc[mf][nf][2] + bb0, acc[mf][nf][3] + bb1);
            *(float2*)(C + (size_t)row       * ldC + col) = v0;
            *(float2*)(C + (size_t)(row + 8) * ldC + col) = v1;
        }
    }
#undef CP_A
#undef LDG_B
#undef STS_B
}

// ---------------- elementwise ----------------
__device__ __forceinline__ float hsig(float x) {
    return fminf(fmaxf(fmaf(0.2f, x, 0.5f), 0.f), 1.f);
}

// round fp32 -> tf32-exact fp32 (float4 per thread)
__global__ void k_round(const float* __restrict__ in, float* __restrict__ out)
{
    int i4 = blockIdx.x * blockDim.x + threadIdx.x;
    float4 vv = *(const float4*)(in + i4 * 4);
    float4 o;
    o.x = f2tff(vv.x); o.y = f2tff(vv.y); o.z = f2tff(vv.z); o.w = f2tff(vv.w);
    *(float4*)(out + i4 * 4) = o;
}

// rh = round(hard_sigmoid(pre_r) * h_tm1)   (r gate = cols 2048..4095 of Pre)
__global__ void k_rh(const float* __restrict__ h,
                     const float* __restrict__ PreR, const float* __restrict__ PreI,
                     float* __restrict__ RH)
{
    int i4 = blockIdx.x * blockDim.x + threadIdx.x;
    int idx = i4 * 4;
    int m  = idx >> 12;
    int j  = idx & 4095;
    int jj = j & 2047;
    float4 pre = (j < 2048) ? *(const float4*)(PreR + m * 4096 + 2048 + jj)
                            : *(const float4*)(PreI + m * 4096 + 2048 + jj);
    float4 hv = *(const float4*)(h + idx);
    float4 o;
    o.x = f2tff(hsig(pre.x) * hv.x);  o.y = f2tff(hsig(pre.y) * hv.y);
    o.z = f2tff(hsig(pre.z) * hv.z);  o.w = f2tff(hsig(pre.w) * hv.w);
    *(float4*)(RH + idx) = o;
}

// h_out = z*h + (1-z)*tanh(Xh + Hh)  (z gate = cols 0..2047 of Pre)
__global__ void k_final(const float* __restrict__ h,
                        const float* __restrict__ PreR, const float* __restrict__ PreI,
                        const float* __restrict__ XhR,  const float* __restrict__ XhI,
                        const float* __restrict__ HhR,  const float* __restrict__ HhI,
                        float* __restrict__ out)
{
    int i4 = blockIdx.x * blockDim.x + threadIdx.x;
    int idx = i4 * 4;
    int m  = idx >> 12;
    int j  = idx & 4095;
    int jj = j & 2047;
    float4 zp, xh, hh4;
    if (j < 2048) {
        zp  = *(const float4*)(PreR + m * 4096 + jj);
        xh  = *(const float4*)(XhR + m * 2048 + jj);
        hh4 = *(const float4*)(HhR + m * 2048 + jj);
    } else {
        zp  = *(const float4*)(PreI + m * 4096 + jj);
        xh  = *(const float4*)(XhI + m * 2048 + jj);
        hh4 = *(const float4*)(HhI + m * 2048 + jj);
    }
    float4 hv = *(const float4*)(h + idx);
    float4 o;
    float z, t;
    z = hsig(zp.x); t = tanhf(xh.x + hh4.x); o.x = z * hv.x + (1.f - z) * t;
    z = hsig(zp.y); t = tanhf(xh.y + hh4.y); o.y = z * hv.y + (1.f - z) * t;
    z = hsig(zp.z); t = tanhf(xh.z + hh4.z); o.z = z * hv.z + (1.f - z) * t;
    z = hsig(zp.w); t = tanhf(xh.w + hh4.w); o.w = z * hv.w + (1.f - z) * t;
    *(float4*)(out + idx) = o;
}

// ---------------- launch ----------------
extern "C" void kernel_launch(void* const* d_in, const int* in_sizes, int n_in,
                              void* d_out, int out_size)
{
    const float* inputs = (const float*)d_in[0];
    const float* h      = (const float*)d_in[1];
    const float* rk     = (const float*)d_in[2];
    const float* ik     = (const float*)d_in[3];
    const float* rrk    = (const float*)d_in[4];
    const float* irk    = (const float*)d_in[5];
    const float* rb     = (const float*)d_in[6];
    const float* ib     = (const float*)d_in[7];
    float* out = (float*)d_out;

    float *PreR, *PreI, *XhR, *XhI, *HhR, *HhI, *RH, *Xr, *Hr;
    cudaGetSymbolAddress((void**)&PreR, g_PreR);
    cudaGetSymbolAddress((void**)&PreI, g_PreI);
    cudaGetSymbolAddress((void**)&XhR,  g_XhR);
    cudaGetSymbolAddress((void**)&XhI,  g_XhI);
    cudaGetSymbolAddress((void**)&HhR,  g_HhR);
    cudaGetSymbolAddress((void**)&HhI,  g_HhI);
    cudaGetSymbolAddress((void**)&RH,   g_RH);
    cudaGetSymbolAddress((void**)&Xr,   g_Xr);
    cudaGetSymbolAddress((void**)&Hr,   g_Hr);

    cudaFuncSetAttribute(gemm_tf32, cudaFuncAttributeMaxDynamicSharedMemorySize, SMEM_TOTAL);
    dim3 blk(128);

    // pre-round activations to tf32
    k_round<<<4096, 256>>>(inputs, Xr);
    k_round<<<4096, 256>>>(h, Hr);

    // Pre (z,r): K=8192 ([x|h]), weight cols 0..4095, bias, C=[1024,4096]
    gemm_tf32<<<dim3(8, 64), blk, SMEM_TOTAL>>>(
        Xr, Hr, rk, ik, rrk, irk, 0, 256, rb, ib, PreR, PreI, 4096);

    // Xh: K=4096 (x), weight cols 4096..6143, bias+4096
    gemm_tf32<<<dim3(8, 32), blk, SMEM_TOTAL>>>(
        Xr, nullptr, rk, ik, rk, ik, 4096, 128,
        rb + 4096, ib + 4096, XhR, XhI, 2048);

    // rh = round(hard_sigmoid(pre_r) * h)
    k_rh<<<4096, 256>>>(h, PreR, PreI, RH);

    // Hh: K=4096 (rh), recurrent cols 4096..6143, no bias
    gemm_tf32<<<dim3(8, 32), blk, SMEM_TOTAL>>>(
        RH, nullptr, rrk, irk, rrk, irk, 4096, 128,
        nullptr, nullptr, HhR, HhI, 2048);

    // combine
    k_final<<<4096, 256>>>(h, PreR, PreI, XhR, XhI, HhR, HhI, out);
}

// round 6
// speedup vs baseline: 1.8883x; 1.8883x over previous
#include <cuda_runtime.h>
#include <cuda_fp16.h>
#include <cstdint>

// ---------------- scratch (device globals) ----------------
__device__ float g_PreR[1024 * 4096];
__device__ float g_PreI[1024 * 4096];
__device__ float g_XhR [1024 * 2048];
__device__ float g_XhI [1024 * 2048];
__device__ float g_HhR [1024 * 2048];
__device__ float g_HhI [1024 * 2048];
__device__ __half g_Wr [2048 * 6144];
__device__ __half g_Wi [2048 * 6144];
__device__ __half g_Rr [2048 * 6144];
__device__ __half g_Ri [2048 * 6144];
__device__ __half g_Xp [1024 * 4096];
__device__ __half g_Xn [1024 * 4096];
__device__ __half g_Hp [1024 * 4096];
__device__ __half g_Hn [1024 * 4096];
__device__ __half g_RHp[1024 * 4096];
__device__ __half g_RHn[1024 * 4096];

__device__ __forceinline__ uint32_t s2u(const void* p) {
    uint32_t a;
    asm("{ .reg .u64 t; cvta.to.shared.u64 t, %1; cvt.u32.u64 %0, t; }" : "=r"(a) : "l"(p));
    return a;
}

#define CP_ASYNC16(dst, src) \
    asm volatile("cp.async.cg.shared.global [%0], [%1], 16;" :: "r"(dst), "l"(src))
#define CP_COMMIT() asm volatile("cp.async.commit_group;" ::: "memory")
#define CP_WAIT1()  asm volatile("cp.async.wait_group 1;" ::: "memory")
#define CP_WAIT0()  asm volatile("cp.async.wait_group 0;" ::: "memory")

// SW128 swizzle on byte offset within a tile of 128B rows
#define SW(o) ((o) ^ (((o) >> 3) & 0x70))

#define LDSM4(r, a) \
    asm volatile("ldmatrix.sync.aligned.m8n8.x4.shared.b16 {%0,%1,%2,%3}, [%4];" \
        : "=r"((r)[0]), "=r"((r)[1]), "=r"((r)[2]), "=r"((r)[3]) : "r"(a))
#define LDSMT4(r, a) \
    asm volatile("ldmatrix.sync.aligned.m8n8.x4.trans.shared.b16 {%0,%1,%2,%3}, [%4];" \
        : "=r"((r)[0]), "=r"((r)[1]), "=r"((r)[2]), "=r"((r)[3]) : "r"(a))

#define MMA16(acc, a, b0, b1) \
    asm volatile("mma.sync.aligned.m16n8k16.row.col.f32.f16.f16.f32 " \
        "{%0,%1,%2,%3},{%4,%5,%6,%7},{%8,%9},{%0,%1,%2,%3};" \
        : "+f"((acc)[0]), "+f"((acc)[1]), "+f"((acc)[2]), "+f"((acc)[3]) \
        : "r"((a)[0]), "r"((a)[1]), "r"((a)[2]), "r"((a)[3]), "r"(b0), "r"(b1))

// smem: 3 stages x (A 16KB + B 16KB); A: 128 m-rows x 64 k (128B rows, SW128);
// B: k-major, 2 panels of [64 k-rows x 64 n] (128B rows, SW128)
#define STAGE      32768
#define SM_B_OFF   16384
#define NSTAGE     3
#define SMEM_TOTAL (NSTAGE * STAGE)

// ---------------------------------------------------------------------------
// fp16 GEMM, fp32 accum: C[1024 x N] = A[1024 x K] @ Wseg (+bias)
// All operands pre-converted to fp16 (rn). Sign handling is baked into the
// negated A copies, so weight tiles stream sign-free via cp.async.
// K in 2048-row segments: seg = kg>>11 picks S0..S3 (v=0) / T0..T3 (v=1).
// A rows k<4096 from a0 else a1. 256 thr = 8 warps, warp tile 64x32.
// grid: x = m-tile (128 rows), y = n-tile*2 + v.
// ---------------------------------------------------------------------------
__global__ void __launch_bounds__(256, 1) gemm_f16(
    const __half* __restrict__ Ap0, const __half* __restrict__ Ap1,
    const __half* __restrict__ An0, const __half* __restrict__ An1,
    const __half* __restrict__ S0, const __half* __restrict__ S1,
    const __half* __restrict__ S2, const __half* __restrict__ S3,
    const __half* __restrict__ T0, const __half* __restrict__ T1,
    const __half* __restrict__ T2, const __half* __restrict__ T3,
    int wcol0, int KT,
    const float* __restrict__ biasR, const float* __restrict__ biasI,
    float* __restrict__ CR, float* __restrict__ CI, int ldC)
{
    extern __shared__ char smem[];
    const uint32_t sb = s2u(smem);

    const int tid  = threadIdx.x;
    const int lane = tid & 31;
    const int warp = tid >> 5;
    const int wm   = warp >> 2;   // 0..1 (64-row warp tile)
    const int wn   = warp & 3;    // 0..3 (32-col warp tile)
    const int bm   = blockIdx.x;
    const int bn   = blockIdx.y >> 1;
    const int v    = blockIdx.y & 1;

    const __half* a0 = v ? An0 : Ap0;
    const __half* a1 = v ? An1 : Ap1;
    const __half* w0 = v ? T0 : S0;
    const __half* w1 = v ? T1 : S1;
    const __half* w2 = v ? T2 : S2;
    const __half* w3 = v ? T3 : S3;
    const float* bias = v ? biasI : biasR;
    float* C = v ? CI : CR;

    float acc[4][4][4];
    #pragma unroll
    for (int i = 0; i < 4; i++)
        #pragma unroll
        for (int j = 0; j < 4; j++)
            #pragma unroll
            for (int k = 0; k < 4; k++) acc[i][j][k] = 0.f;

    // ---- producer coords ----
    const int arow = tid >> 1;            // 0..127
    const int ac0  = (tid & 1) * 4;       // chunk base 0 or 4 (of 8)
    const int brow = tid >> 2;            // 0..63
    const int bc0  = (tid & 3) * 4;       // chunk base (of 16)
    const size_t mBase = (size_t)(bm * 128);
    const int    gn    = wcol0 + bn * 128;

    // ---- consumer (ldmatrix) constants ----
    const uint32_t xorv = (lane & 7) << 4;
    const uint32_t l87  = (lane & 7) + ((lane >> 3) & 1) * 8;
    const uint32_t aRowOff = (wm * 64 + l87) * 128;
    const uint32_t bRowOff = SM_B_OFF + (wn >> 1) * 8192 +
                             ((lane >> 3) * 8 + (lane & 7)) * 128;
    uint32_t aoff[4], boffn[4];
    #pragma unroll
    for (int s = 0; s < 4; s++)
        aoff[s] = (uint32_t)(s * 32 + (lane >> 4) * 16) ^ xorv;
    #pragma unroll
    for (int nf = 0; nf < 4; nf++)
        boffn[nf] = (uint32_t)(((wn & 1) * 32 + nf * 8) * 2) ^ xorv;

#define CP_STAGE(KT_IDX)                                                            \
    do {                                                                            \
        const int kg = (KT_IDX) * 64;                                               \
        const uint32_t sbase = sb + ((KT_IDX) % NSTAGE) * STAGE;                    \
        const __half* asrc = ((kg >= 4096) ? a1 : a0) +                             \
                             (mBase + arow) * 4096 + (kg & 4095) + ac0 * 8;         \
        _Pragma("unroll")                                                           \
        for (int i = 0; i < 4; i++)                                                 \
            CP_ASYNC16(sbase + SW(arow * 128 + (ac0 + i) * 16), asrc + i * 8);      \
        const int seg = kg >> 11;                                                   \
        const __half* Wp = (seg == 0) ? w0 : (seg == 1) ? w1 : (seg == 2) ? w2 : w3;\
        const __half* bsrc = Wp + (size_t)((kg & 2047) + brow) * 6144 + gn;         \
        _Pragma("unroll")                                                           \
        for (int i = 0; i < 4; i++) {                                               \
            const int ch = bc0 + i, p = ch >> 3, cc = ch & 7;                       \
            CP_ASYNC16(sbase + SM_B_OFF + p * 8192 + SW(brow * 128 + cc * 16),      \
                       bsrc + p * 64 + cc * 8);                                     \
        }                                                                           \
        CP_COMMIT();                                                                \
    } while (0)

    // ---- prologue: stages 0,1 in flight ----
    CP_STAGE(0);
    CP_STAGE(1);
    CP_WAIT1();          // stage 0 complete
    __syncthreads();

    for (int kt = 0; kt < KT; ++kt) {
        if (kt + 2 < KT) CP_STAGE(kt + 2);

        const uint32_t base = sb + (kt % NSTAGE) * STAGE;

        #pragma unroll
        for (int kh = 0; kh < 2; kh++) {       // 32-k halves
            uint32_t bfr[4][4];
            #pragma unroll
            for (int nf = 0; nf < 4; nf++)
                LDSMT4(bfr[nf], base + bRowOff + kh * 4096 + boffn[nf]);
            #pragma unroll
            for (int sh = 0; sh < 2; sh++) {   // k16 steps
                const int s = kh * 2 + sh;
                uint32_t afr[4][4];
                #pragma unroll
                for (int mf = 0; mf < 4; mf++)
                    LDSM4(afr[mf], base + aRowOff + mf * 2048 + aoff[s]);
                #pragma unroll
                for (int mf = 0; mf < 4; mf++)
                    #pragma unroll
                    for (int nf = 0; nf < 4; nf++)
                        MMA16(acc[mf][nf], afr[mf], bfr[nf][sh * 2], bfr[nf][sh * 2 + 1]);
            }
        }

        if (kt + 1 < KT) {
            if (kt + 2 < KT) CP_WAIT1(); else CP_WAIT0();
            __syncthreads();
        }
    }

    // ---- epilogue ----
    const int gid = lane >> 2;
    const int tig = lane & 3;
    #pragma unroll
    for (int mf = 0; mf < 4; mf++) {
        const int row = bm * 128 + wm * 64 + mf * 16 + gid;
        #pragma unroll
        for (int nf = 0; nf < 4; nf++) {
            const int col = bn * 128 + wn * 32 + nf * 8 + tig * 2;
            float bb0 = 0.f, bb1 = 0.f;
            if (bias) { bb0 = bias[col]; bb1 = bias[col + 1]; }
            float2 v0 = make_float2(acc[mf][nf][0] + bb0, acc[mf][nf][1] + bb1);
            float2 v1 = make_float2(acc[mf][nf][2] + bb0, acc[mf][nf][3] + bb1);
            *(float2*)(C + (size_t)row       * ldC + col) = v0;
            *(float2*)(C + (size_t)(row + 8) * ldC + col) = v1;
        }
    }
#undef CP_STAGE
}

// ---------------- elementwise ----------------
__device__ __forceinline__ float hsig(float x) {
    return fminf(fmaxf(fmaf(0.2f, x, 0.5f), 0.f), 1.f);
}
__device__ __forceinline__ uint2 pack4(float a, float b, float c, float d) {
    __half2 lo = __floats2half2_rn(a, b);
    __half2 hi = __floats2half2_rn(c, d);
    uint2 o;
    o.x = *(uint32_t*)&lo;
    o.y = *(uint32_t*)&hi;
    return o;
}

// fp32 weight -> fp16
__global__ void k_w2h(const float4* __restrict__ in, uint2* __restrict__ out)
{
    int i = blockIdx.x * blockDim.x + threadIdx.x;
    float4 vv = in[i];
    out[i] = pack4(vv.x, vv.y, vv.z, vv.w);
}

// activation fp32 -> fp16 positive copy + first-half-negated copy
__global__ void k_xh2h(const float* __restrict__ in,
                       __half* __restrict__ outp, __half* __restrict__ outn)
{
    int i4 = blockIdx.x * blockDim.x + threadIdx.x;
    int idx = i4 * 4;
    float4 vv = *(const float4*)(in + idx);
    *(uint2*)(outp + idx) = pack4(vv.x, vv.y, vv.z, vv.w);
    float s = ((idx & 4095) < 2048) ? -1.f : 1.f;
    *(uint2*)(outn + idx) = pack4(s * vv.x, s * vv.y, s * vv.z, s * vv.w);
}

// rh = hard_sigmoid(pre_r) * h_tm1 -> fp16 (positive + first-half-negated)
__global__ void k_rh(const float* __restrict__ h,
                     const float* __restrict__ PreR, const float* __restrict__ PreI,
                     __half* __restrict__ RHp, __half* __restrict__ RHn)
{
    int i4 = blockIdx.x * blockDim.x + threadIdx.x;
    int idx = i4 * 4;
    int m  = idx >> 12;
    int j  = idx & 4095;
    int jj = j & 2047;
    float4 pre = (j < 2048) ? *(const float4*)(PreR + m * 4096 + 2048 + jj)
                            : *(const float4*)(PreI + m * 4096 + 2048 + jj);
    float4 hv = *(const float4*)(h + idx);
    float a = hsig(pre.x) * hv.x, b = hsig(pre.y) * hv.y;
    float c = hsig(pre.z) * hv.z, d = hsig(pre.w) * hv.w;
    *(uint2*)(RHp + idx) = pack4(a, b, c, d);
    float s = (j < 2048) ? -1.f : 1.f;
    *(uint2*)(RHn + idx) = pack4(s * a, s * b, s * c, s * d);
}

// h_out = z*h + (1-z)*tanh(Xh + Hh)
__global__ void k_final(const float* __restrict__ h,
                        const float* __restrict__ PreR, const float* __restrict__ PreI,
                        const float* __restrict__ XhR,  const float* __restrict__ XhI,
                        const float* __restrict__ HhR,  const float* __restrict__ HhI,
                        float* __restrict__ out)
{
    int i4 = blockIdx.x * blockDim.x + threadIdx.x;
    int idx = i4 * 4;
    int m  = idx >> 12;
    int j  = idx & 4095;
    int jj = j & 2047;
    float4 zp, xh, hh4;
    if (j < 2048) {
        zp  = *(const float4*)(PreR + m * 4096 + jj);
        xh  = *(const float4*)(XhR + m * 2048 + jj);
        hh4 = *(const float4*)(HhR + m * 2048 + jj);
    } else {
        zp  = *(const float4*)(PreI + m * 4096 + jj);
        xh  = *(const float4*)(XhI + m * 2048 + jj);
        hh4 = *(const float4*)(HhI + m * 2048 + jj);
    }
    float4 hv = *(const float4*)(h + idx);
    float4 o;
    float z, t;
    z = hsig(zp.x); t = tanhf(xh.x + hh4.x); o.x = z * hv.x + (1.f - z) * t;
    z = hsig(zp.y); t = tanhf(xh.y + hh4.y); o.y = z * hv.y + (1.f - z) * t;
    z = hsig(zp.z); t = tanhf(xh.z + hh4.z); o.z = z * hv.z + (1.f - z) * t;
    z = hsig(zp.w); t = tanhf(xh.w + hh4.w); o.w = z * hv.w + (1.f - z) * t;
    *(float4*)(out + idx) = o;
}

// ---------------- launch ----------------
extern "C" void kernel_launch(void* const* d_in, const int* in_sizes, int n_in,
                              void* d_out, int out_size)
{
    const float* inputs = (const float*)d_in[0];
    const float* h      = (const float*)d_in[1];
    const float* rk     = (const float*)d_in[2];
    const float* ik     = (const float*)d_in[3];
    const float* rrk    = (const float*)d_in[4];
    const float* irk    = (const float*)d_in[5];
    const float* rb     = (const float*)d_in[6];
    const float* ib     = (const float*)d_in[7];
    float* out = (float*)d_out;

    float *PreR, *PreI, *XhR, *XhI, *HhR, *HhI;
    __half *Wr, *Wi, *Rr, *Ri, *Xp, *Xn, *Hp, *Hn, *RHp, *RHn;
    cudaGetSymbolAddress((void**)&PreR, g_PreR);
    cudaGetSymbolAddress((void**)&PreI, g_PreI);
    cudaGetSymbolAddress((void**)&XhR,  g_XhR);
    cudaGetSymbolAddress((void**)&XhI,  g_XhI);
    cudaGetSymbolAddress((void**)&HhR,  g_HhR);
    cudaGetSymbolAddress((void**)&HhI,  g_HhI);
    cudaGetSymbolAddress((void**)&Wr,   g_Wr);
    cudaGetSymbolAddress((void**)&Wi,   g_Wi);
    cudaGetSymbolAddress((void**)&Rr,   g_Rr);
    cudaGetSymbolAddress((void**)&Ri,   g_Ri);
    cudaGetSymbolAddress((void**)&Xp,   g_Xp);
    cudaGetSymbolAddress((void**)&Xn,   g_Xn);
    cudaGetSymbolAddress((void**)&Hp,   g_Hp);
    cudaGetSymbolAddress((void**)&Hn,   g_Hn);
    cudaGetSymbolAddress((void**)&RHp,  g_RHp);
    cudaGetSymbolAddress((void**)&RHn,  g_RHn);

    cudaFuncSetAttribute(gemm_f16, cudaFuncAttributeMaxDynamicSharedMemorySize, SMEM_TOTAL);
    dim3 blk(256);

    // fp16 conversions
    k_w2h<<<12288, 256>>>((const float4*)rk,  (uint2*)Wr);
    k_w2h<<<12288, 256>>>((const float4*)ik,  (uint2*)Wi);
    k_w2h<<<12288, 256>>>((const float4*)rrk, (uint2*)Rr);
    k_w2h<<<12288, 256>>>((const float4*)irk, (uint2*)Ri);
    k_xh2h<<<4096, 256>>>(inputs, Xp, Xn);
    k_xh2h<<<4096, 256>>>(h, Hp, Hn);

    // Pre (z,r): K=8192 ([x|h]), weight cols 0..4095, bias, C=[1024,4096]
    // v0 segs: [Wr, Wi, Rr, Ri] with A=[Xp|Hp]; v1: [Wi, Wr, Ri, Rr] with A=[Xn|Hn]
    gemm_f16<<<dim3(8, 64), blk, SMEM_TOTAL>>>(
        Xp, Hp, Xn, Hn,
        Wr, Wi, Rr, Ri,  Wi, Wr, Ri, Rr,
        0, 128, rb, ib, PreR, PreI, 4096);

    // Xh: K=4096 (x), weight cols 4096..6143
    gemm_f16<<<dim3(8, 32), blk, SMEM_TOTAL>>>(
        Xp, Xp, Xn, Xn,
        Wr, Wi, Wr, Wi,  Wi, Wr, Wi, Wr,
        4096, 64, rb + 4096, ib + 4096, XhR, XhI, 2048);

    // rh = hard_sigmoid(pre_r) * h  -> fp16 copies
    k_rh<<<4096, 256>>>(h, PreR, PreI, RHp, RHn);

    // Hh: K=4096 (rh), recurrent cols 4096..6143, no bias
    gemm_f16<<<dim3(8, 32), blk, SMEM_TOTAL>>>(
        RHp, RHp, RHn, RHn,
        Rr, Ri, Rr, Ri,  Ri, Rr, Ri, Rr,
        4096, 64, nullptr, nullptr, HhR, HhI, 2048);

    // combine
    k_final<<<4096, 256>>>(h, PreR, PreI, XhR, XhI, HhR, HhI, out);
}

// round 7
// speedup vs baseline: 2.4029x; 1.2725x over previous
#include <cuda_runtime.h>
#include <cuda_fp16.h>
#include <cstdint>

// ---------------- scratch (device globals) ----------------
__device__ float g_PreR[1024 * 4096];
__device__ float g_PreI[1024 * 4096];
__device__ float g_XhR [1024 * 2048];
__device__ float g_XhI [1024 * 2048];
__device__ float g_HhR [1024 * 2048];
__device__ float g_HhI [1024 * 2048];
__device__ __half g_Wr [2048 * 6144];
__device__ __half g_Wi [2048 * 6144];
__device__ __half g_Rr [2048 * 6144];
__device__ __half g_Ri [2048 * 6144];
__device__ __half g_Xp [1024 * 4096];
__device__ __half g_Xn [1024 * 4096];
__device__ __half g_Hp [1024 * 4096];
__device__ __half g_Hn [1024 * 4096];
__device__ __half g_RHp[1024 * 4096];
__device__ __half g_RHn[1024 * 4096];

__device__ __forceinline__ uint32_t s2u(const void* p) {
    uint32_t a;
    asm("{ .reg .u64 t; cvta.to.shared.u64 t, %1; cvt.u32.u64 %0, t; }" : "=r"(a) : "l"(p));
    return a;
}

#define CP_ASYNC16(dst, src) \
    asm volatile("cp.async.cg.shared.global [%0], [%1], 16;" :: "r"(dst), "l"(src))
#define CP_COMMIT() asm volatile("cp.async.commit_group;" ::: "memory")
#define CP_WAIT1()  asm volatile("cp.async.wait_group 1;" ::: "memory")
#define CP_WAIT0()  asm volatile("cp.async.wait_group 0;" ::: "memory")

// SW128 swizzle on byte offset within a tile of 128B rows
#define SW(o) ((o) ^ (((o) >> 3) & 0x70))

#define LDSM4(r, a) \
    asm volatile("ldmatrix.sync.aligned.m8n8.x4.shared.b16 {%0,%1,%2,%3}, [%4];" \
        : "=r"((r)[0]), "=r"((r)[1]), "=r"((r)[2]), "=r"((r)[3]) : "r"(a))
#define LDSMT4(r, a) \
    asm volatile("ldmatrix.sync.aligned.m8n8.x4.trans.shared.b16 {%0,%1,%2,%3}, [%4];" \
        : "=r"((r)[0]), "=r"((r)[1]), "=r"((r)[2]), "=r"((r)[3]) : "r"(a))

#define MMA16(acc, a, b0, b1) \
    asm volatile("mma.sync.aligned.m16n8k16.row.col.f32.f16.f16.f32 " \
        "{%0,%1,%2,%3},{%4,%5,%6,%7},{%8,%9},{%0,%1,%2,%3};" \
        : "+f"((acc)[0]), "+f"((acc)[1]), "+f"((acc)[2]), "+f"((acc)[3]) \
        : "r"((a)[0]), "r"((a)[1]), "r"((a)[2]), "r"((a)[3]), "r"(b0), "r"(b1))

// smem: 3 stages x (A 16KB + B 16KB); A: 128 m-rows x 64 k (128B rows, SW128);
// B: k-major, 2 panels of [64 k-rows x 64 n] (128B rows, SW128)
#define STAGE      32768
#define SM_B_OFF   16384
#define NSTAGE     3
#define SMEM_TOTAL (NSTAGE * STAGE)

// ---------------------------------------------------------------------------
// fp16 GEMM, fp32 accum: C[1024 x N] = A[1024 x K] @ Wseg (+bias)
// All operands pre-converted to fp16 (rn). Sign handling is baked into the
// negated A copies, so weight tiles stream sign-free via cp.async.
// K in 2048-row segments: seg = kg>>11 picks S0..S3 (v=0) / T0..T3 (v=1).
// A rows k<4096 from a0 else a1. 256 thr = 8 warps, warp tile 64x32.
// 2 CTAs/SM for latency hiding. grid: x = m-tile, y = n-tile*2 + v.
// ---------------------------------------------------------------------------
__global__ void __launch_bounds__(256, 2) gemm_f16(
    const __half* __restrict__ Ap0, const __half* __restrict__ Ap1,
    const __half* __restrict__ An0, const __half* __restrict__ An1,
    const __half* __restrict__ S0, const __half* __restrict__ S1,
    const __half* __restrict__ S2, const __half* __restrict__ S3,
    const __half* __restrict__ T0, const __half* __restrict__ T1,
    const __half* __restrict__ T2, const __half* __restrict__ T3,
    int wcol0, int KT,
    const float* __restrict__ biasR, const float* __restrict__ biasI,
    float* __restrict__ CR, float* __restrict__ CI, int ldC)
{
    extern __shared__ char smem[];
    const uint32_t sb = s2u(smem);

    const int tid  = threadIdx.x;
    const int lane = tid & 31;
    const int warp = tid >> 5;
    const int wm   = warp >> 2;   // 0..1 (64-row warp tile)
    const int wn   = warp & 3;    // 0..3 (32-col warp tile)
    const int bm   = blockIdx.x;
    const int bn   = blockIdx.y >> 1;
    const int v    = blockIdx.y & 1;

    const __half* a0 = v ? An0 : Ap0;
    const __half* a1 = v ? An1 : Ap1;
    const __half* w0 = v ? T0 : S0;
    const __half* w1 = v ? T1 : S1;
    const __half* w2 = v ? T2 : S2;
    const __half* w3 = v ? T3 : S3;
    const float* bias = v ? biasI : biasR;
    float* C = v ? CI : CR;

    float acc[4][4][4];
    #pragma unroll
    for (int i = 0; i < 4; i++)
        #pragma unroll
        for (int j = 0; j < 4; j++)
            #pragma unroll
            for (int k = 0; k < 4; k++) acc[i][j][k] = 0.f;

    // ---- producer coords ----
    const int arow = tid >> 1;            // 0..127
    const int ac0  = (tid & 1) * 4;       // chunk base 0 or 4 (of 8)
    const int brow = tid >> 2;            // 0..63
    const int bc0  = (tid & 3) * 4;       // chunk base (of 16)
    const size_t mBase = (size_t)(bm * 128);
    const int    gn    = wcol0 + bn * 128;

    // ---- consumer (ldmatrix) constants ----
    const uint32_t xorv = (lane & 7) << 4;
    const uint32_t l87  = (lane & 7) + ((lane >> 3) & 1) * 8;
    const uint32_t aRowOff = (wm * 64 + l87) * 128;
    const uint32_t bRowOff = SM_B_OFF + (wn >> 1) * 8192 +
                             ((lane >> 3) * 8 + (lane & 7)) * 128;
    uint32_t aoff[4], boffn[4];
    #pragma unroll
    for (int s = 0; s < 4; s++)
        aoff[s] = (uint32_t)(s * 32 + (lane >> 4) * 16) ^ xorv;
    #pragma unroll
    for (int nf = 0; nf < 4; nf++)
        boffn[nf] = (uint32_t)(((wn & 1) * 32 + nf * 8) * 2) ^ xorv;

#define CP_STAGE(KT_IDX)                                                            \
    do {                                                                            \
        const int kg = (KT_IDX) * 64;                                               \
        const uint32_t sbase = sb + ((KT_IDX) % NSTAGE) * STAGE;                    \
        const __half* asrc = ((kg >= 4096) ? a1 : a0) +                             \
                             (mBase + arow) * 4096 + (kg & 4095) + ac0 * 8;         \
        _Pragma("unroll")                                                           \
        for (int i = 0; i < 4; i++)                                                 \
            CP_ASYNC16(sbase + SW(arow * 128 + (ac0 + i) * 16), asrc + i * 8);      \
        const int seg = kg >> 11;                                                   \
        const __half* Wp = (seg == 0) ? w0 : (seg == 1) ? w1 : (seg == 2) ? w2 : w3;\
        const __half* bsrc = Wp + (size_t)((kg & 2047) + brow) * 6144 + gn;         \
        _Pragma("unroll")                                                           \
        for (int i = 0; i < 4; i++) {                                               \
            const int ch = bc0 + i, p = ch >> 3, cc = ch & 7;                       \
            CP_ASYNC16(sbase + SM_B_OFF + p * 8192 + SW(brow * 128 + cc * 16),      \
                       bsrc + p * 64 + cc * 8);                                     \
        }                                                                           \
        CP_COMMIT();                                                                \
    } while (0)

    // ---- prologue: stages 0,1 in flight ----
    CP_STAGE(0);
    CP_STAGE(1);
    CP_WAIT1();          // stage 0 complete
    __syncthreads();

    for (int kt = 0; kt < KT; ++kt) {
        if (kt + 2 < KT) CP_STAGE(kt + 2);

        const uint32_t base = sb + (kt % NSTAGE) * STAGE;

        #pragma unroll
        for (int kh = 0; kh < 2; kh++) {       // 32-k halves
            uint32_t bfr[4][4];
            #pragma unroll
            for (int nf = 0; nf < 4; nf++)
                LDSMT4(bfr[nf], base + bRowOff + kh * 4096 + boffn[nf]);
            #pragma unroll
            for (int sh = 0; sh < 2; sh++) {   // k16 steps
                const int s = kh * 2 + sh;
                uint32_t afr[4][4];
                #pragma unroll
                for (int mf = 0; mf < 4; mf++)
                    LDSM4(afr[mf], base + aRowOff + mf * 2048 + aoff[s]);
                #pragma unroll
                for (int mf = 0; mf < 4; mf++)
                    #pragma unroll
                    for (int nf = 0; nf < 4; nf++)
                        MMA16(acc[mf][nf], afr[mf], bfr[nf][sh * 2], bfr[nf][sh * 2 + 1]);
            }
        }

        if (kt + 1 < KT) {
            if (kt + 2 < KT) CP_WAIT1(); else CP_WAIT0();
            __syncthreads();
        }
    }

    // ---- epilogue ----
    const int gid = lane >> 2;
    const int tig = lane & 3;
    #pragma unroll
    for (int mf = 0; mf < 4; mf++) {
        const int row = bm * 128 + wm * 64 + mf * 16 + gid;
        #pragma unroll
        for (int nf = 0; nf < 4; nf++) {
            const int col = bn * 128 + wn * 32 + nf * 8 + tig * 2;
            float bb0 = 0.f, bb1 = 0.f;
            if (bias) { bb0 = bias[col]; bb1 = bias[col + 1]; }
            float2 v0 = make_float2(acc[mf][nf][0] + bb0, acc[mf][nf][1] + bb1);
            float2 v1 = make_float2(acc[mf][nf][2] + bb0, acc[mf][nf][3] + bb1);
            *(float2*)(C + (size_t)row       * ldC + col) = v0;
            *(float2*)(C + (size_t)(row + 8) * ldC + col) = v1;
        }
    }
#undef CP_STAGE
}

// ---------------- elementwise ----------------
__device__ __forceinline__ float hsig(float x) {
    return fminf(fmaxf(fmaf(0.2f, x, 0.5f), 0.f), 1.f);
}
__device__ __forceinline__ uint2 pack4(float a, float b, float c, float d) {
    __half2 lo = __floats2half2_rn(a, b);
    __half2 hi = __floats2half2_rn(c, d);
    uint2 o;
    o.x = *(uint32_t*)&lo;
    o.y = *(uint32_t*)&hi;
    return o;
}

// fp32 weights -> fp16, all four matrices in one launch (y picks matrix)
__global__ void k_w2h4(const float4* __restrict__ s0, const float4* __restrict__ s1,
                       const float4* __restrict__ s2, const float4* __restrict__ s3,
                       uint2* __restrict__ d0, uint2* __restrict__ d1,
                       uint2* __restrict__ d2, uint2* __restrict__ d3)
{
    const int w = blockIdx.y;
    const float4* in = (w == 0) ? s0 : (w == 1) ? s1 : (w == 2) ? s2 : s3;
    uint2* out      = (w == 0) ? d0 : (w == 1) ? d1 : (w == 2) ? d2 : d3;
    int i = blockIdx.x * blockDim.x + threadIdx.x;
    float4 vv = in[i];
    out[i] = pack4(vv.x, vv.y, vv.z, vv.w);
}

// activation fp32 -> fp16 positive copy + first-half-negated copy
__global__ void k_xh2h(const float* __restrict__ in,
                       __half* __restrict__ outp, __half* __restrict__ outn)
{
    int i4 = blockIdx.x * blockDim.x + threadIdx.x;
    int idx = i4 * 4;
    float4 vv = *(const float4*)(in + idx);
    *(uint2*)(outp + idx) = pack4(vv.x, vv.y, vv.z, vv.w);
    float s = ((idx & 4095) < 2048) ? -1.f : 1.f;
    *(uint2*)(outn + idx) = pack4(s * vv.x, s * vv.y, s * vv.z, s * vv.w);
}

// rh = hard_sigmoid(pre_r) * h_tm1 -> fp16 (positive + first-half-negated)
__global__ void k_rh(const float* __restrict__ h,
                     const float* __restrict__ PreR, const float* __restrict__ PreI,
                     __half* __restrict__ RHp, __half* __restrict__ RHn)
{
    int i4 = blockIdx.x * blockDim.x + threadIdx.x;
    int idx = i4 * 4;
    int m  = idx >> 12;
    int j  = idx & 4095;
    int jj = j & 2047;
    float4 pre = (j < 2048) ? *(const float4*)(PreR + m * 4096 + 2048 + jj)
                            : *(const float4*)(PreI + m * 4096 + 2048 + jj);
    float4 hv = *(const float4*)(h + idx);
    float a = hsig(pre.x) * hv.x, b = hsig(pre.y) * hv.y;
    float c = hsig(pre.z) * hv.z, d = hsig(pre.w) * hv.w;
    *(uint2*)(RHp + idx) = pack4(a, b, c, d);
    float s = (j < 2048) ? -1.f : 1.f;
    *(uint2*)(RHn + idx) = pack4(s * a, s * b, s * c, s * d);
}

// h_out = z*h + (1-z)*tanh(Xh + Hh)
__global__ void k_final(const float* __restrict__ h,
                        const float* __restrict__ PreR, const float* __restrict__ PreI,
                        const float* __restrict__ XhR,  const float* __restrict__ XhI,
                        const float* __restrict__ HhR,  const float* __restrict__ HhI,
                        float* __restrict__ out)
{
    int i4 = blockIdx.x * blockDim.x + threadIdx.x;
    int idx = i4 * 4;
    int m  = idx >> 12;
    int j  = idx & 4095;
    int jj = j & 2047;
    float4 zp, xh, hh4;
    if (j < 2048) {
        zp  = *(const float4*)(PreR + m * 4096 + jj);
        xh  = *(const float4*)(XhR + m * 2048 + jj);
        hh4 = *(const float4*)(HhR + m * 2048 + jj);
    } else {
        zp  = *(const float4*)(PreI + m * 4096 + jj);
        xh  = *(const float4*)(XhI + m * 2048 + jj);
        hh4 = *(const float4*)(HhI + m * 2048 + jj);
    }
    float4 hv = *(const float4*)(h + idx);
    float4 o;
    float z, t;
    z = hsig(zp.x); t = tanhf(xh.x + hh4.x); o.x = z * hv.x + (1.f - z) * t;
    z = hsig(zp.y); t = tanhf(xh.y + hh4.y); o.y = z * hv.y + (1.f - z) * t;
    z = hsig(zp.z); t = tanhf(xh.z + hh4.z); o.z = z * hv.z + (1.f - z) * t;
    z = hsig(zp.w); t = tanhf(xh.w + hh4.w); o.w = z * hv.w + (1.f - z) * t;
    *(float4*)(out + idx) = o;
}

// ---------------- launch ----------------
extern "C" void kernel_launch(void* const* d_in, const int* in_sizes, int n_in,
                              void* d_out, int out_size)
{
    const float* inputs = (const float*)d_in[0];
    const float* h      = (const float*)d_in[1];
    const float* rk     = (const float*)d_in[2];
    const float* ik     = (const float*)d_in[3];
    const float* rrk    = (const float*)d_in[4];
    const float* irk    = (const float*)d_in[5];
    const float* rb     = (const float*)d_in[6];
    const float* ib     = (const float*)d_in[7];
    float* out = (float*)d_out;

    float *PreR, *PreI, *XhR, *XhI, *HhR, *HhI;
    __half *Wr, *Wi, *Rr, *Ri, *Xp, *Xn, *Hp, *Hn, *RHp, *RHn;
    cudaGetSymbolAddress((void**)&PreR, g_PreR);
    cudaGetSymbolAddress((void**)&PreI, g_PreI);
    cudaGetSymbolAddress((void**)&XhR,  g_XhR);
    cudaGetSymbolAddress((void**)&XhI,  g_XhI);
    cudaGetSymbolAddress((void**)&HhR,  g_HhR);
    cudaGetSymbolAddress((void**)&HhI,  g_HhI);
    cudaGetSymbolAddress((void**)&Wr,   g_Wr);
    cudaGetSymbolAddress((void**)&Wi,   g_Wi);
    cudaGetSymbolAddress((void**)&Rr,   g_Rr);
    cudaGetSymbolAddress((void**)&Ri,   g_Ri);
    cudaGetSymbolAddress((void**)&Xp,   g_Xp);
    cudaGetSymbolAddress((void**)&Xn,   g_Xn);
    cudaGetSymbolAddress((void**)&Hp,   g_Hp);
    cudaGetSymbolAddress((void**)&Hn,   g_Hn);
    cudaGetSymbolAddress((void**)&RHp,  g_RHp);
    cudaGetSymbolAddress((void**)&RHn,  g_RHn);

    cudaFuncSetAttribute(gemm_f16, cudaFuncAttributeMaxDynamicSharedMemorySize, SMEM_TOTAL);
    dim3 blk(256);

    // fp16 conversions (single launch for all 4 weight matrices)
    k_w2h4<<<dim3(12288, 4), 256>>>((const float4*)rk, (const float4*)ik,
                                    (const float4*)rrk, (const float4*)irk,
                                    (uint2*)Wr, (uint2*)Wi, (uint2*)Rr, (uint2*)Ri);
    k_xh2h<<<4096, 256>>>(inputs, Xp, Xn);
    k_xh2h<<<4096, 256>>>(h, Hp, Hn);

    // Pre (z,r): K=8192 ([x|h]), weight cols 0..4095, bias, C=[1024,4096]
    // v0 segs: [Wr, Wi, Rr, Ri] with A=[Xp|Hp]; v1: [Wi, Wr, Ri, Rr] with A=[Xn|Hn]
    gemm_f16<<<dim3(8, 64), blk, SMEM_TOTAL>>>(
        Xp, Hp, Xn, Hn,
        Wr, Wi, Rr, Ri,  Wi, Wr, Ri, Rr,
        0, 128, rb, ib, PreR, PreI, 4096);

    // Xh: K=4096 (x), weight cols 4096..6143
    gemm_f16<<<dim3(8, 32), blk, SMEM_TOTAL>>>(
        Xp, Xp, Xn, Xn,
        Wr, Wi, Wr, Wi,  Wi, Wr, Wi, Wr,
        4096, 64, rb + 4096, ib + 4096, XhR, XhI, 2048);

    // rh = hard_sigmoid(pre_r) * h  -> fp16 copies
    k_rh<<<4096, 256>>>(h, PreR, PreI, RHp, RHn);

    // Hh: K=4096 (rh), recurrent cols 4096..6143, no bias
    gemm_f16<<<dim3(8, 32), blk, SMEM_TOTAL>>>(
        RHp, RHp, RHn, RHn,
        Rr, Ri, Rr, Ri,  Ri, Rr, Ri, Rr,
        4096, 64, nullptr, nullptr, HhR, HhI, 2048);

    // combine
    k_final<<<4096, 256>>>(h, PreR, PreI, XhR, XhI, HhR, HhI, out);
}

// round 8
// speedup vs baseline: 2.7575x; 1.1476x over previous
#include <cuda_runtime.h>
#include <cuda_fp16.h>
#include <cstdint>

// ---------------- scratch (device globals) ----------------
__device__ float g_PreR[1024 * 4096];
__device__ float g_PreI[1024 * 4096];
__device__ float g_XhR [1024 * 2048];
__device__ float g_XhI [1024 * 2048];
__device__ float g_HhR [1024 * 2048];
__device__ float g_HhI [1024 * 2048];
__device__ float g_K1p [1024 * 4096];   // Gauss k1 for Pre
__device__ float g_K1x [1024 * 2048];   // k1 for Xh
__device__ float g_K1h [1024 * 2048];   // k1 for Hh
// weights fp16: plain, -(W+Wi), (W-Wi) for kernel + recurrent
__device__ __half g_Wr [2048 * 6144];
__device__ __half g_Rr [2048 * 6144];
__device__ __half g_Wnn[2048 * 6144];
__device__ __half g_Rnn[2048 * 6144];
__device__ __half g_Wdd[2048 * 6144];
__device__ __half g_Rdd[2048 * 6144];
// activations fp16: halves + sums (compact [1024 x 2048])
__device__ __half g_X1[1024 * 2048];
__device__ __half g_X2[1024 * 2048];
__device__ __half g_XS[1024 * 2048];
__device__ __half g_H1[1024 * 2048];
__device__ __half g_H2[1024 * 2048];
__device__ __half g_HS[1024 * 2048];
__device__ __half g_R1[1024 * 2048];
__device__ __half g_R2[1024 * 2048];
__device__ __half g_RS[1024 * 2048];

__device__ __forceinline__ uint32_t s2u(const void* p) {
    uint32_t a;
    asm("{ .reg .u64 t; cvta.to.shared.u64 t, %1; cvt.u32.u64 %0, t; }" : "=r"(a) : "l"(p));
    return a;
}

#define CP_ASYNC16(dst, src) \
    asm volatile("cp.async.cg.shared.global [%0], [%1], 16;" :: "r"(dst), "l"(src))
#define CP_COMMIT() asm volatile("cp.async.commit_group;" ::: "memory")
#define CP_WAIT1()  asm volatile("cp.async.wait_group 1;" ::: "memory")
#define CP_WAIT0()  asm volatile("cp.async.wait_group 0;" ::: "memory")

#define SW(o) ((o) ^ (((o) >> 3) & 0x70))

#define LDSM4(r, a) \
    asm volatile("ldmatrix.sync.aligned.m8n8.x4.shared.b16 {%0,%1,%2,%3}, [%4];" \
        : "=r"((r)[0]), "=r"((r)[1]), "=r"((r)[2]), "=r"((r)[3]) : "r"(a))
#define LDSMT4(r, a) \
    asm volatile("ldmatrix.sync.aligned.m8n8.x4.trans.shared.b16 {%0,%1,%2,%3}, [%4];" \
        : "=r"((r)[0]), "=r"((r)[1]), "=r"((r)[2]), "=r"((r)[3]) : "r"(a))

#define MMA16(acc, a, b0, b1) \
    asm volatile("mma.sync.aligned.m16n8k16.row.col.f32.f16.f16.f32 " \
        "{%0,%1,%2,%3},{%4,%5,%6,%7},{%8,%9},{%0,%1,%2,%3};" \
        : "+f"((acc)[0]), "+f"((acc)[1]), "+f"((acc)[2]), "+f"((acc)[3]) \
        : "r"((a)[0]), "r"((a)[1]), "r"((a)[2]), "r"((a)[3]), "r"(b0), "r"(b1))

#define STAGE      32768
#define SM_B_OFF   16384
#define NSTAGE     3
#define SMEM_TOTAL (NSTAGE * STAGE)

// problem descriptor: C = Kin + sgn*(sum_seg A_s @ B_s[wcol..]) + bias
struct GP {
    const __half *A0, *A1;     // per-2048-K-segment activation [1024 x 2048]
    const __half *B0, *B1;     // per-segment weight [2048 x 6144]
    const float  *Kin;         // optional combine input (same shape as C)
    const float  *bias;        // optional bias[col]
    float        *C;
    int wcol, nseg, ldC;
    float sgn;
};

// ---------------------------------------------------------------------------
// generic fp16 GEMM, fp32 accum; up to 4 problems per launch selected by
// blockIdx.y ranges [0,y1), [y1,y2), [y2,y3), [y3,...). 256 thr, 8 warps,
// CTA tile 128x128, warp 64x32, 3-stage cp.async, 2 CTAs/SM.
// ---------------------------------------------------------------------------
__global__ void __launch_bounds__(256, 2) gemm_g(
    GP p0, GP p1, GP p2, GP p3, int y1, int y2, int y3)
{
    extern __shared__ char smem[];
    const uint32_t sb = s2u(smem);

    const int tid  = threadIdx.x;
    const int lane = tid & 31;
    const int warp = tid >> 5;
    const int wm   = warp >> 2;
    const int wn   = warp & 3;
    const int bm   = blockIdx.x;
    const int by   = blockIdx.y;

#define SEL(f) ((by < y1) ? p0.f : (by < y2) ? p1.f : (by < y3) ? p2.f : p3.f)
    const __half* A0 = SEL(A0);
    const __half* A1 = SEL(A1);
    const __half* B0 = SEL(B0);
    const __half* B1 = SEL(B1);
    const float*  Kin  = SEL(Kin);
    const float*  bias = SEL(bias);
    float*        C    = SEL(C);
    const int wcol = SEL(wcol);
    const int nseg = SEL(nseg);
    const int ldC  = SEL(ldC);
    const float sg = SEL(sgn);
#undef SEL
    const int bn = by - ((by < y1) ? 0 : (by < y2) ? y1 : (by < y3) ? y2 : y3);
    const int KT = nseg << 5;

    float acc[4][4][4];
    #pragma unroll
    for (int i = 0; i < 4; i++)
        #pragma unroll
        for (int j = 0; j < 4; j++)
            #pragma unroll
            for (int k = 0; k < 4; k++) acc[i][j][k] = 0.f;

    const int arow = tid >> 1;
    const int ac0  = (tid & 1) * 4;
    const int brow = tid >> 2;
    const int bc0  = (tid & 3) * 4;
    const size_t mBase = (size_t)(bm * 128);
    const int    gn    = wcol + bn * 128;

    const uint32_t xorv = (lane & 7) << 4;
    const uint32_t l87  = (lane & 7) + ((lane >> 3) & 1) * 8;
    const uint32_t aRowOff = (wm * 64 + l87) * 128;
    const uint32_t bRowOff = SM_B_OFF + (wn >> 1) * 8192 +
                             ((lane >> 3) * 8 + (lane & 7)) * 128;
    uint32_t aoff[4], boffn[4];
    #pragma unroll
    for (int s = 0; s < 4; s++)
        aoff[s] = (uint32_t)(s * 32 + (lane >> 4) * 16) ^ xorv;
    #pragma unroll
    for (int nf = 0; nf < 4; nf++)
        boffn[nf] = (uint32_t)(((wn & 1) * 32 + nf * 8) * 2) ^ xorv;

#define CP_STAGE(KT_IDX)                                                            \
    do {                                                                            \
        const int kg = (KT_IDX) * 64;                                               \
        const int klocal = kg & 2047;                                               \
        const uint32_t sbase = sb + ((KT_IDX) % NSTAGE) * STAGE;                    \
        const __half* Ap = (kg >= 2048) ? A1 : A0;                                  \
        const __half* asrc = Ap + (mBase + arow) * 2048 + klocal + ac0 * 8;         \
        _Pragma("unroll")                                                           \
        for (int i = 0; i < 4; i++)                                                 \
            CP_ASYNC16(sbase + SW(arow * 128 + (ac0 + i) * 16), asrc + i * 8);      \
        const __half* Bp = (kg >= 2048) ? B1 : B0;                                  \
        const __half* bsrc = Bp + (size_t)(klocal + brow) * 6144 + gn;              \
        _Pragma("unroll")                                                           \
        for (int i = 0; i < 4; i++) {                                               \
            const int ch = bc0 + i, pp = ch >> 3, cc = ch & 7;                      \
            CP_ASYNC16(sbase + SM_B_OFF + pp * 8192 + SW(brow * 128 + cc * 16),     \
                       bsrc + pp * 64 + cc * 8);                                    \
        }                                                                           \
        CP_COMMIT();                                                                \
    } while (0)

    CP_STAGE(0);
    CP_STAGE(1);
    CP_WAIT1();
    __syncthreads();

    for (int kt = 0; kt < KT; ++kt) {
        if (kt + 2 < KT) CP_STAGE(kt + 2);

        const uint32_t base = sb + (kt % NSTAGE) * STAGE;

        #pragma unroll
        for (int kh = 0; kh < 2; kh++) {
            uint32_t bfr[4][4];
            #pragma unroll
            for (int nf = 0; nf < 4; nf++)
                LDSMT4(bfr[nf], base + bRowOff + kh * 4096 + boffn[nf]);
            #pragma unroll
            for (int sh = 0; sh < 2; sh++) {
                const int s = kh * 2 + sh;
                uint32_t afr[4][4];
                #pragma unroll
                for (int mf = 0; mf < 4; mf++)
                    LDSM4(afr[mf], base + aRowOff + mf * 2048 + aoff[s]);
                #pragma unroll
                for (int mf = 0; mf < 4; mf++)
                    #pragma unroll
                    for (int nf = 0; nf < 4; nf++)
                        MMA16(acc[mf][nf], afr[mf], bfr[nf][sh * 2], bfr[nf][sh * 2 + 1]);
            }
        }

        if (kt + 1 < KT) {
            if (kt + 2 < KT) CP_WAIT1(); else CP_WAIT0();
            __syncthreads();
        }
    }

    // epilogue: C = Kin + sgn*acc + bias
    const int gid = lane >> 2;
    const int tig = lane & 3;
    #pragma unroll
    for (int mf = 0; mf < 4; mf++) {
        const int row = bm * 128 + wm * 64 + mf * 16 + gid;
        #pragma unroll
        for (int nf = 0; nf < 4; nf++) {
            const int col = bn * 128 + wn * 32 + nf * 8 + tig * 2;
            float b0 = 0.f, b1 = 0.f;
            if (bias) { b0 = bias[col]; b1 = bias[col + 1]; }
            if (Kin) {
                float2 k0 = *(const float2*)(Kin + (size_t)row * ldC + col);
                float2 k1v = *(const float2*)(Kin + (size_t)(row + 8) * ldC + col);
                b0 += 0.f; b1 += 0.f;
                float2 v0 = make_float2(k0.x + sg * acc[mf][nf][0] + b0,
                                        k0.y + sg * acc[mf][nf][1] + b1);
                float2 v1 = make_float2(k1v.x + sg * acc[mf][nf][2] + b0,
                                        k1v.y + sg * acc[mf][nf][3] + b1);
                *(float2*)(C + (size_t)row       * ldC + col) = v0;
                *(float2*)(C + (size_t)(row + 8) * ldC + col) = v1;
            } else {
                float2 v0 = make_float2(sg * acc[mf][nf][0] + b0, sg * acc[mf][nf][1] + b1);
                float2 v1 = make_float2(sg * acc[mf][nf][2] + b0, sg * acc[mf][nf][3] + b1);
                *(float2*)(C + (size_t)row       * ldC + col) = v0;
                *(float2*)(C + (size_t)(row + 8) * ldC + col) = v1;
            }
        }
    }
#undef CP_STAGE
}

// ---------------- elementwise ----------------
__device__ __forceinline__ float hsig(float x) {
    return fminf(fmaxf(fmaf(0.2f, x, 0.5f), 0.f), 1.f);
}
__device__ __forceinline__ uint2 pack4(float a, float b, float c, float d) {
    __half2 lo = __floats2half2_rn(a, b);
    __half2 hi = __floats2half2_rn(c, d);
    uint2 o;
    o.x = *(uint32_t*)&lo;
    o.y = *(uint32_t*)&hi;
    return o;
}

// weight prep: y = 0..5 -> Wr, Rr, Wnn, Rnn, Wdd, Rdd
__global__ void k_wprep(const float4* __restrict__ rk,  const float4* __restrict__ ik,
                        const float4* __restrict__ rrk, const float4* __restrict__ irk,
                        uint2* __restrict__ Wr,  uint2* __restrict__ Rr,
                        uint2* __restrict__ Wnn, uint2* __restrict__ Rnn,
                        uint2* __restrict__ Wdd, uint2* __restrict__ Rdd)
{
    const int w = blockIdx.y;
    int i = blockIdx.x * blockDim.x + threadIdx.x;
    const float4* a = (w == 0 || w == 2 || w == 4) ? rk : rrk;
    const float4* b = (w == 0 || w == 2 || w == 4) ? ik : irk;
    if (w == 1 || w == 3 || w == 5) { a = rrk; b = irk; }
    else { a = rk; b = ik; }
    float4 va = a[i];
    uint2* out;
    float4 o;
    if (w < 2) {                     // plain
        o = va;
        out = (w == 0) ? Wr : Rr;
    } else if (w < 4) {              // -(r+i)
        float4 vb = b[i];
        o.x = -(va.x + vb.x); o.y = -(va.y + vb.y);
        o.z = -(va.z + vb.z); o.w = -(va.w + vb.w);
        out = (w == 2) ? Wnn : Rnn;
    } else {                         // r - i
        float4 vb = b[i];
        o.x = va.x - vb.x; o.y = va.y - vb.y;
        o.z = va.z - vb.z; o.w = va.w - vb.w;
        out = (w == 4) ? Wdd : Rdd;
    }
    out[i] = pack4(o.x, o.y, o.z, o.w);
}

// activations -> halves + sum (fp16, compact stride 2048); y=0: inputs, y=1: h
__global__ void k_acts(const float* __restrict__ x, const float* __restrict__ h,
                       __half* __restrict__ X1, __half* __restrict__ X2, __half* __restrict__ XS,
                       __half* __restrict__ H1, __half* __restrict__ H2, __half* __restrict__ HS)
{
    const float* in = blockIdx.y ? h : x;
    __half *o1 = blockIdx.y ? H1 : X1, *o2 = blockIdx.y ? H2 : X2, *os = blockIdx.y ? HS : XS;
    int i4 = blockIdx.x * blockDim.x + threadIdx.x;   // over 1024*2048/4
    int idx = i4 * 4;
    int m = idx >> 11, j = idx & 2047;
    float4 v1 = *(const float4*)(in + (size_t)m * 4096 + j);
    float4 v2 = *(const float4*)(in + (size_t)m * 4096 + 2048 + j);
    *(uint2*)(o1 + idx) = pack4(v1.x, v1.y, v1.z, v1.w);
    *(uint2*)(o2 + idx) = pack4(v2.x, v2.y, v2.z, v2.w);
    *(uint2*)(os + idx) = pack4(v1.x + v2.x, v1.y + v2.y, v1.z + v2.z, v1.w + v2.w);
}

// rh halves + sum from r gate (Pre cols 2048..4095)
__global__ void k_rh(const float* __restrict__ h,
                     const float* __restrict__ PreR, const float* __restrict__ PreI,
                     __half* __restrict__ R1, __half* __restrict__ R2, __half* __restrict__ RS)
{
    int i4 = blockIdx.x * blockDim.x + threadIdx.x;   // over 1024*2048/4
    int idx = i4 * 4;
    int m = idx >> 11, j = idx & 2047;
    float4 p1 = *(const float4*)(PreR + (size_t)m * 4096 + 2048 + j);
    float4 p2 = *(const float4*)(PreI + (size_t)m * 4096 + 2048 + j);
    float4 h1 = *(const float4*)(h + (size_t)m * 4096 + j);
    float4 h2 = *(const float4*)(h + (size_t)m * 4096 + 2048 + j);
    float a1 = hsig(p1.x) * h1.x, b1 = hsig(p1.y) * h1.y,
          c1 = hsig(p1.z) * h1.z, d1 = hsig(p1.w) * h1.w;
    float a2 = hsig(p2.x) * h2.x, b2 = hsig(p2.y) * h2.y,
          c2 = hsig(p2.z) * h2.z, d2 = hsig(p2.w) * h2.w;
    *(uint2*)(R1 + idx) = pack4(a1, b1, c1, d1);
    *(uint2*)(R2 + idx) = pack4(a2, b2, c2, d2);
    *(uint2*)(RS + idx) = pack4(a1 + a2, b1 + b2, c1 + c2, d1 + d2);
}

// h_out = z*h + (1-z)*tanh(Xh + Hh)
__global__ void k_final(const float* __restrict__ h,
                        const float* __restrict__ PreR, const float* __restrict__ PreI,
                        const float* __restrict__ XhR,  const float* __restrict__ XhI,
                        const float* __restrict__ HhR,  const float* __restrict__ HhI,
                        float* __restrict__ out)
{
    int i4 = blockIdx.x * blockDim.x + threadIdx.x;
    int idx = i4 * 4;
    int m  = idx >> 12;
    int j  = idx & 4095;
    int jj = j & 2047;
    float4 zp, xh, hh4;
    if (j < 2048) {
        zp  = *(const float4*)(PreR + (size_t)m * 4096 + jj);
        xh  = *(const float4*)(XhR + (size_t)m * 2048 + jj);
        hh4 = *(const float4*)(HhR + (size_t)m * 2048 + jj);
    } else {
        zp  = *(const float4*)(PreI + (size_t)m * 4096 + jj);
        xh  = *(const float4*)(XhI + (size_t)m * 2048 + jj);
        hh4 = *(const float4*)(HhI + (size_t)m * 2048 + jj);
    }
    float4 hv = *(const float4*)(h + idx);
    float4 o;
    float z, t;
    z = hsig(zp.x); t = tanhf(xh.x + hh4.x); o.x = z * hv.x + (1.f - z) * t;
    z = hsig(zp.y); t = tanhf(xh.y + hh4.y); o.y = z * hv.y + (1.f - z) * t;
    z = hsig(zp.z); t = tanhf(xh.z + hh4.z); o.z = z * hv.z + (1.f - z) * t;
    z = hsig(zp.w); t = tanhf(xh.w + hh4.w); o.w = z * hv.w + (1.f - z) * t;
    *(float4*)(out + idx) = o;
}

// ---------------- launch ----------------
extern "C" void kernel_launch(void* const* d_in, const int* in_sizes, int n_in,
                              void* d_out, int out_size)
{
    const float* inputs = (const float*)d_in[0];
    const float* h      = (const float*)d_in[1];
    const float* rk     = (const float*)d_in[2];
    const float* ik     = (const float*)d_in[3];
    const float* rrk    = (const float*)d_in[4];
    const float* irk    = (const float*)d_in[5];
    const float* rb     = (const float*)d_in[6];
    const float* ib     = (const float*)d_in[7];
    float* out = (float*)d_out;

    float *PreR, *PreI, *XhR, *XhI, *HhR, *HhI, *K1p, *K1x, *K1h;
    __half *Wr, *Rr, *Wnn, *Rnn, *Wdd, *Rdd;
    __half *X1, *X2, *XS, *H1, *H2, *HS, *R1, *R2, *RS;
    cudaGetSymbolAddress((void**)&PreR, g_PreR);
    cudaGetSymbolAddress((void**)&PreI, g_PreI);
    cudaGetSymbolAddress((void**)&XhR,  g_XhR);
    cudaGetSymbolAddress((void**)&XhI,  g_XhI);
    cudaGetSymbolAddress((void**)&HhR,  g_HhR);
    cudaGetSymbolAddress((void**)&HhI,  g_HhI);
    cudaGetSymbolAddress((void**)&K1p,  g_K1p);
    cudaGetSymbolAddress((void**)&K1x,  g_K1x);
    cudaGetSymbolAddress((void**)&K1h,  g_K1h);
    cudaGetSymbolAddress((void**)&Wr,   g_Wr);
    cudaGetSymbolAddress((void**)&Rr,   g_Rr);
    cudaGetSymbolAddress((void**)&Wnn,  g_Wnn);
    cudaGetSymbolAddress((void**)&Rnn,  g_Rnn);
    cudaGetSymbolAddress((void**)&Wdd,  g_Wdd);
    cudaGetSymbolAddress((void**)&Rdd,  g_Rdd);
    cudaGetSymbolAddress((void**)&X1,   g_X1);
    cudaGetSymbolAddress((void**)&X2,   g_X2);
    cudaGetSymbolAddress((void**)&XS,   g_XS);
    cudaGetSymbolAddress((void**)&H1,   g_H1);
    cudaGetSymbolAddress((void**)&H2,   g_H2);
    cudaGetSymbolAddress((void**)&HS,   g_HS);
    cudaGetSymbolAddress((void**)&R1,   g_R1);
    cudaGetSymbolAddress((void**)&R2,   g_R2);
    cudaGetSymbolAddress((void**)&RS,   g_RS);

    cudaFuncSetAttribute(gemm_g, cudaFuncAttributeMaxDynamicSharedMemorySize, SMEM_TOTAL);

    // prep
    k_wprep<<<dim3(12288, 6), 256>>>((const float4*)rk, (const float4*)ik,
                                     (const float4*)rrk, (const float4*)irk,
                                     (uint2*)Wr, (uint2*)Rr, (uint2*)Wnn,
                                     (uint2*)Rnn, (uint2*)Wdd, (uint2*)Rdd);
    k_acts<<<dim3(2048, 2), 256>>>(inputs, h, X1, X2, XS, H1, H2, HS);

    GP z{};   // dummy

    // L1: k1 GEMMs.  Pre-k1: (XS@Wr + HS@Rr) cols 0..4095 -> K1p
    //                Xh-k1:  XS@Wr cols 4096..6143 -> K1x
    GP preK1{XS, HS, Wr, Rr, nullptr, nullptr, K1p, 0,    2, 4096, 1.f};
    GP xhK1 {XS, XS, Wr, Wr, nullptr, nullptr, K1x, 4096, 1, 2048, 1.f};
    gemm_g<<<dim3(8, 48), 256, SMEM_TOTAL>>>(preK1, xhK1, xhK1, xhK1, 32, 48, 48);

    // L2: k2/k3 + combine.
    //  PreI = K1p + (X1@Wnn + H1@Rnn) + ib
    //  PreR = K1p - (X2@Wdd + H2@Rdd) + rb
    //  XhI  = K1x + X1@Wnn + ib[4096..]
    //  XhR  = K1x - X2@Wdd + rb[4096..]
    GP preI{X1, H1, Wnn, Rnn, K1p, ib,        PreI, 0,    2, 4096,  1.f};
    GP preR{X2, H2, Wdd, Rdd, K1p, rb,        PreR, 0,    2, 4096, -1.f};
    GP xhI {X1, X1, Wnn, Wnn, K1x, ib + 4096, XhI,  4096, 1, 2048,  1.f};
    GP xhR {X2, X2, Wdd, Wdd, K1x, rb + 4096, XhR,  4096, 1, 2048, -1.f};
    gemm_g<<<dim3(8, 96), 256, SMEM_TOTAL>>>(preI, preR, xhI, xhR, 32, 64, 80);

    // rh halves + sum
    k_rh<<<2048, 256>>>(h, PreR, PreI, R1, R2, RS);

    // L3: Hh-k1 = RS@Rr cols 4096.. -> K1h
    GP hhK1{RS, RS, Rr, Rr, nullptr, nullptr, K1h, 4096, 1, 2048, 1.f};
    gemm_g<<<dim3(8, 16), 256, SMEM_TOTAL>>>(hhK1, hhK1, hhK1, hhK1, 16, 16, 16);

    // L4: HhI = K1h + R1@Rnn ; HhR = K1h - R2@Rdd
    GP hhI{R1, R1, Rnn, Rnn, K1h, nullptr, HhI, 4096, 1, 2048,  1.f};
    GP hhR{R2, R2, Rdd, Rdd, K1h, nullptr, HhR, 4096, 1, 2048, -1.f};
    gemm_g<<<dim3(8, 32), 256, SMEM_TOTAL>>>(hhI, hhR, hhR, hhR, 16, 32, 32);

    // combine
    k_final<<<4096, 256>>>(h, PreR, PreI, XhR, XhI, HhR, HhI, out);
}

// round 9
// speedup vs baseline: 2.8941x; 1.0495x over previous
#include <cuda_runtime.h>
#include <cuda_fp16.h>
#include <cstdint>

// ---------------- scratch (device globals) ----------------
__device__ float g_PreR[1024 * 4096];
__device__ float g_PreI[1024 * 4096];
__device__ float g_XhR [1024 * 2048];
__device__ float g_XhI [1024 * 2048];
__device__ float g_HhR [1024 * 2048];
__device__ float g_HhI [1024 * 2048];
__device__ float g_K1p [1024 * 4096];   // Gauss k1 for Pre
__device__ float g_K1x [1024 * 2048];   // k1 for Xh
__device__ float g_K1h [1024 * 2048];   // k1 for Hh
// weights fp16: plain, -(W+Wi), (W-Wi) for kernel + recurrent
__device__ __half g_Wr [2048 * 6144];
__device__ __half g_Rr [2048 * 6144];
__device__ __half g_Wnn[2048 * 6144];
__device__ __half g_Rnn[2048 * 6144];
__device__ __half g_Wdd[2048 * 6144];
__device__ __half g_Rdd[2048 * 6144];
// activations fp16: halves + sums (compact [1024 x 2048])
__device__ __half g_X1[1024 * 2048];
__device__ __half g_X2[1024 * 2048];
__device__ __half g_XS[1024 * 2048];
__device__ __half g_H1[1024 * 2048];
__device__ __half g_H2[1024 * 2048];
__device__ __half g_HS[1024 * 2048];
__device__ __half g_R1[1024 * 2048];
__device__ __half g_R2[1024 * 2048];
__device__ __half g_RS[1024 * 2048];

__device__ __forceinline__ uint32_t s2u(const void* p) {
    uint32_t a;
    asm("{ .reg .u64 t; cvta.to.shared.u64 t, %1; cvt.u32.u64 %0, t; }" : "=r"(a) : "l"(p));
    return a;
}

#define CP_ASYNC16(dst, src) \
    asm volatile("cp.async.cg.shared.global [%0], [%1], 16;" :: "r"(dst), "l"(src))
#define CP_COMMIT() asm volatile("cp.async.commit_group;" ::: "memory")
#define CP_WAIT1()  asm volatile("cp.async.wait_group 1;" ::: "memory")
#define CP_WAIT0()  asm volatile("cp.async.wait_group 0;" ::: "memory")

#define SW(o) ((o) ^ (((o) >> 3) & 0x70))

#define LDSM4(r, a) \
    asm volatile("ldmatrix.sync.aligned.m8n8.x4.shared.b16 {%0,%1,%2,%3}, [%4];" \
        : "=r"((r)[0]), "=r"((r)[1]), "=r"((r)[2]), "=r"((r)[3]) : "r"(a))
#define LDSMT4(r, a) \
    asm volatile("ldmatrix.sync.aligned.m8n8.x4.trans.shared.b16 {%0,%1,%2,%3}, [%4];" \
        : "=r"((r)[0]), "=r"((r)[1]), "=r"((r)[2]), "=r"((r)[3]) : "r"(a))

#define MMA16(acc, a, b0, b1) \
    asm volatile("mma.sync.aligned.m16n8k16.row.col.f32.f16.f16.f32 " \
        "{%0,%1,%2,%3},{%4,%5,%6,%7},{%8,%9},{%0,%1,%2,%3};" \
        : "+f"((acc)[0]), "+f"((acc)[1]), "+f"((acc)[2]), "+f"((acc)[3]) \
        : "r"((a)[0]), "r"((a)[1]), "r"((a)[2]), "r"((a)[3]), "r"(b0), "r"(b1))

#define STAGE      32768
#define SM_B_OFF   16384
#define NSTAGE     3
#define SMEM_TOTAL (NSTAGE * STAGE)

// problem descriptor: C = Kin + sgn*(sum_seg A_s @ B_s[wcol..]) + bias
struct GP {
    const __half *A0, *A1;     // per-2048-K-segment activation [1024 x 2048]
    const __half *B0, *B1;     // per-segment weight [2048 x 6144]
    const float  *Kin;         // optional combine input (same shape as C)
    const float  *bias;        // optional bias[col]
    float        *C;
    int wcol, nseg, ldC;
    float sgn;
};

// ---------------------------------------------------------------------------
// generic fp16 GEMM, fp32 accum; up to 4 problems per launch selected by
// blockIdx.y ranges. 256 thr, 8 warps, CTA 128x128, warp 64x32, 3-stage
// cp.async pipeline, double-buffered A fragments, 2 CTAs/SM.
// ---------------------------------------------------------------------------
__global__ void __launch_bounds__(256, 2) gemm_g(
    GP p0, GP p1, GP p2, GP p3, int y1, int y2, int y3)
{
    extern __shared__ char smem[];
    const uint32_t sb = s2u(smem);

    const int tid  = threadIdx.x;
    const int lane = tid & 31;
    const int warp = tid >> 5;
    const int wm   = warp >> 2;
    const int wn   = warp & 3;
    const int bm   = blockIdx.x;
    const int by   = blockIdx.y;

#define SEL(f) ((by < y1) ? p0.f : (by < y2) ? p1.f : (by < y3) ? p2.f : p3.f)
    const __half* A0 = SEL(A0);
    const __half* A1 = SEL(A1);
    const __half* B0 = SEL(B0);
    const __half* B1 = SEL(B1);
    const int wcol = SEL(wcol);
    const int nseg = SEL(nseg);
    const int bn = by - ((by < y1) ? 0 : (by < y2) ? y1 : (by < y3) ? y2 : y3);
    const int KT = nseg << 5;

    float acc[4][4][4];
    #pragma unroll
    for (int i = 0; i < 4; i++)
        #pragma unroll
        for (int j = 0; j < 4; j++)
            #pragma unroll
            for (int k = 0; k < 4; k++) acc[i][j][k] = 0.f;

    const int arow = tid >> 1;
    const int ac0  = (tid & 1) * 4;
    const int brow = tid >> 2;
    const int bc0  = (tid & 3) * 4;
    const size_t mBase = (size_t)(bm * 128);
    const int    gn    = wcol + bn * 128;

    const uint32_t xorv = (lane & 7) << 4;
    const uint32_t l87  = (lane & 7) + ((lane >> 3) & 1) * 8;
    const uint32_t aRowOff = (wm * 64 + l87) * 128;
    const uint32_t bRowOff = SM_B_OFF + (wn >> 1) * 8192 +
                             ((lane >> 3) * 8 + (lane & 7)) * 128;
    const uint32_t p16c = (lane >> 4) * 16;
    const uint32_t bsel = (wn & 1) * 64;

#define CP_STAGE(KT_IDX)                                                            \
    do {                                                                            \
        const int kg = (KT_IDX) * 64;                                               \
        const int klocal = kg & 2047;                                               \
        const uint32_t sbase = sb + ((KT_IDX) % NSTAGE) * STAGE;                    \
        const __half* Ap = (kg >= 2048) ? A1 : A0;                                  \
        const __half* asrc = Ap + (mBase + arow) * 2048 + klocal + ac0 * 8;         \
        _Pragma("unroll")                                                           \
        for (int i = 0; i < 4; i++)                                                 \
            CP_ASYNC16(sbase + SW(arow * 128 + (ac0 + i) * 16), asrc + i * 8);      \
        const __half* Bp = (kg >= 2048) ? B1 : B0;                                  \
        const __half* bsrc = Bp + (size_t)(klocal + brow) * 6144 + gn;              \
        _Pragma("unroll")                                                           \
        for (int i = 0; i < 4; i++) {                                               \
            const int ch = bc0 + i, pp = ch >> 3, cc = ch & 7;                      \
            CP_ASYNC16(sbase + SM_B_OFF + pp * 8192 + SW(brow * 128 + cc * 16),     \
                       bsrc + pp * 64 + cc * 8);                                    \
        }                                                                           \
        CP_COMMIT();                                                                \
    } while (0)

#define LDA(dst, BASE, S)                                                           \
    do {                                                                            \
        const uint32_t off = ((uint32_t)((S) * 32) + p16c) ^ xorv;                  \
        _Pragma("unroll")                                                           \
        for (int mf = 0; mf < 4; mf++)                                              \
            LDSM4((dst)[mf], (BASE) + aRowOff + mf * 2048 + off);                   \
    } while (0)

#define LDB(dst, BASE, KH)                                                          \
    do {                                                                            \
        _Pragma("unroll")                                                           \
        for (int nf = 0; nf < 4; nf++)                                              \
            LDSMT4((dst)[nf], (BASE) + bRowOff + (KH) * 4096 +                      \
                   (((uint32_t)(bsel + nf * 16)) ^ xorv));                          \
    } while (0)

    uint32_t afr[2][4][4];
    uint32_t bfr[4][4];

    CP_STAGE(0);
    CP_STAGE(1);
    CP_WAIT1();
    __syncthreads();

    for (int kt = 0; kt < KT; ++kt) {
        const uint32_t base = sb + (kt % NSTAGE) * STAGE;

        LDA(afr[0], base, 0);               // hidden behind CP_STAGE issue below
        if (kt + 2 < KT) CP_STAGE(kt + 2);

        #pragma unroll
        for (int s = 0; s < 4; s++) {
            if ((s & 1) == 0) LDB(bfr, base, s >> 1);
            if (s < 3) LDA(afr[(s + 1) & 1], base, s + 1);
            const int sh = s & 1;
            #pragma unroll
            for (int mf = 0; mf < 4; mf++)
                #pragma unroll
                for (int nf = 0; nf < 4; nf++)
                    MMA16(acc[mf][nf], afr[s & 1][mf],
                          bfr[nf][sh * 2], bfr[nf][sh * 2 + 1]);
        }

        if (kt + 1 < KT) {
            if (kt + 2 < KT) CP_WAIT1(); else CP_WAIT0();
            __syncthreads();
        }
    }

    // epilogue (params selected late so they are not live in the mainloop)
    const float* Kin  = SEL(Kin);
    const float* bias = SEL(bias);
    float*       C    = SEL(C);
    const int    ldC  = SEL(ldC);
    const float  sg   = SEL(sgn);
#undef SEL

    const int gid = lane >> 2;
    const int tig = lane & 3;
    #pragma unroll
    for (int mf = 0; mf < 4; mf++) {
        const int row = bm * 128 + wm * 64 + mf * 16 + gid;
        #pragma unroll
        for (int nf = 0; nf < 4; nf++) {
            const int col = bn * 128 + wn * 32 + nf * 8 + tig * 2;
            float b0 = 0.f, b1 = 0.f;
            if (bias) { b0 = bias[col]; b1 = bias[col + 1]; }
            float k00 = 0.f, k01 = 0.f, k10 = 0.f, k11 = 0.f;
            if (Kin) {
                float2 ka = *(const float2*)(Kin + (size_t)row * ldC + col);
                float2 kb = *(const float2*)(Kin + (size_t)(row + 8) * ldC + col);
                k00 = ka.x; k01 = ka.y; k10 = kb.x; k11 = kb.y;
            }
            float2 v0 = make_float2(k00 + sg * acc[mf][nf][0] + b0,
                                    k01 + sg * acc[mf][nf][1] + b1);
            float2 v1 = make_float2(k10 + sg * acc[mf][nf][2] + b0,
                                    k11 + sg * acc[mf][nf][3] + b1);
            *(float2*)(C + (size_t)row       * ldC + col) = v0;
            *(float2*)(C + (size_t)(row + 8) * ldC + col) = v1;
        }
    }
#undef CP_STAGE
#undef LDA
#undef LDB
}

// ---------------- elementwise ----------------
__device__ __forceinline__ float hsig(float x) {
    return fminf(fmaxf(fmaf(0.2f, x, 0.5f), 0.f), 1.f);
}
__device__ __forceinline__ uint2 pack4(float a, float b, float c, float d) {
    __half2 lo = __floats2half2_rn(a, b);
    __half2 hi = __floats2half2_rn(c, d);
    uint2 o;
    o.x = *(uint32_t*)&lo;
    o.y = *(uint32_t*)&hi;
    return o;
}

// weight prep (read-once): Wr/Wnn/Wdd from rk,ik; Rr/Rnn/Rdd from rrk,irk
__global__ void k_wprep(const float4* __restrict__ rk,  const float4* __restrict__ ik,
                        const float4* __restrict__ rrk, const float4* __restrict__ irk,
                        uint2* __restrict__ Wr,  uint2* __restrict__ Rr,
                        uint2* __restrict__ Wnn, uint2* __restrict__ Rnn,
                        uint2* __restrict__ Wdd, uint2* __restrict__ Rdd)
{
    int i = blockIdx.x * blockDim.x + threadIdx.x;
    float4 a = rk[i], b = ik[i];
    Wr[i]  = pack4(a.x, a.y, a.z, a.w);
    Wnn[i] = pack4(-(a.x + b.x), -(a.y + b.y), -(a.z + b.z), -(a.w + b.w));
    Wdd[i] = pack4(a.x - b.x, a.y - b.y, a.z - b.z, a.w - b.w);
    float4 c = rrk[i], d = irk[i];
    Rr[i]  = pack4(c.x, c.y, c.z, c.w);
    Rnn[i] = pack4(-(c.x + d.x), -(c.y + d.y), -(c.z + d.z), -(c.w + d.w));
    Rdd[i] = pack4(c.x - d.x, c.y - d.y, c.z - d.z, c.w - d.w);
}

// activations -> halves + sum (fp16, compact stride 2048); y=0: inputs, y=1: h
__global__ void k_acts(const float* __restrict__ x, const float* __restrict__ h,
                       __half* __restrict__ X1, __half* __restrict__ X2, __half* __restrict__ XS,
                       __half* __restrict__ H1, __half* __restrict__ H2, __half* __restrict__ HS)
{
    const float* in = blockIdx.y ? h : x;
    __half *o1 = blockIdx.y ? H1 : X1, *o2 = blockIdx.y ? H2 : X2, *os = blockIdx.y ? HS : XS;
    int i4 = blockIdx.x * blockDim.x + threadIdx.x;
    int idx = i4 * 4;
    int m = idx >> 11, j = idx & 2047;
    float4 v1 = *(const float4*)(in + (size_t)m * 4096 + j);
    float4 v2 = *(const float4*)(in + (size_t)m * 4096 + 2048 + j);
    *(uint2*)(o1 + idx) = pack4(v1.x, v1.y, v1.z, v1.w);
    *(uint2*)(o2 + idx) = pack4(v2.x, v2.y, v2.z, v2.w);
    *(uint2*)(os + idx) = pack4(v1.x + v2.x, v1.y + v2.y, v1.z + v2.z, v1.w + v2.w);
}

// rh halves + sum from r gate (Pre cols 2048..4095)
__global__ void k_rh(const float* __restrict__ h,
                     const float* __restrict__ PreR, const float* __restrict__ PreI,
                     __half* __restrict__ R1, __half* __restrict__ R2, __half* __restrict__ RS)
{
    int i4 = blockIdx.x * blockDim.x + threadIdx.x;
    int idx = i4 * 4;
    int m = idx >> 11, j = idx & 2047;
    float4 p1 = *(const float4*)(PreR + (size_t)m * 4096 + 2048 + j);
    float4 p2 = *(const float4*)(PreI + (size_t)m * 4096 + 2048 + j);
    float4 h1 = *(const float4*)(h + (size_t)m * 4096 + j);
    float4 h2 = *(const float4*)(h + (size_t)m * 4096 + 2048 + j);
    float a1 = hsig(p1.x) * h1.x, b1 = hsig(p1.y) * h1.y,
          c1 = hsig(p1.z) * h1.z, d1 = hsig(p1.w) * h1.w;
    float a2 = hsig(p2.x) * h2.x, b2 = hsig(p2.y) * h2.y,
          c2 = hsig(p2.z) * h2.z, d2 = hsig(p2.w) * h2.w;
    *(uint2*)(R1 + idx) = pack4(a1, b1, c1, d1);
    *(uint2*)(R2 + idx) = pack4(a2, b2, c2, d2);
    *(uint2*)(RS + idx) = pack4(a1 + a2, b1 + b2, c1 + c2, d1 + d2);
}

// h_out = z*h + (1-z)*tanh(Xh + Hh)
__global__ void k_final(const float* __restrict__ h,
                        const float* __restrict__ PreR, const float* __restrict__ PreI,
                        const float* __restrict__ XhR,  const float* __restrict__ XhI,
                        const float* __restrict__ HhR,  const float* __restrict__ HhI,
                        float* __restrict__ out)
{
    int i4 = blockIdx.x * blockDim.x + threadIdx.x;
    int idx = i4 * 4;
    int m  = idx >> 12;
    int j  = idx & 4095;
    int jj = j & 2047;
    float4 zp, xh, hh4;
    if (j < 2048) {
        zp  = *(const float4*)(PreR + (size_t)m * 4096 + jj);
        xh  = *(const float4*)(XhR + (size_t)m * 2048 + jj);
        hh4 = *(const float4*)(HhR + (size_t)m * 2048 + jj);
    } else {
        zp  = *(const float4*)(PreI + (size_t)m * 4096 + jj);
        xh  = *(const float4*)(XhI + (size_t)m * 2048 + jj);
        hh4 = *(const float4*)(HhI + (size_t)m * 2048 + jj);
    }
    float4 hv = *(const float4*)(h + idx);
    float4 o;
    float z, t;
    z = hsig(zp.x); t = tanhf(xh.x + hh4.x); o.x = z * hv.x + (1.f - z) * t;
    z = hsig(zp.y); t = tanhf(xh.y + hh4.y); o.y = z * hv.y + (1.f - z) * t;
    z = hsig(zp.z); t = tanhf(xh.z + hh4.z); o.z = z * hv.z + (1.f - z) * t;
    z = hsig(zp.w); t = tanhf(xh.w + hh4.w); o.w = z * hv.w + (1.f - z) * t;
    *(float4*)(out + idx) = o;
}

// ---------------- launch ----------------
extern "C" void kernel_launch(void* const* d_in, const int* in_sizes, int n_in,
                              void* d_out, int out_size)
{
    const float* inputs = (const float*)d_in[0];
    const float* h      = (const float*)d_in[1];
    const float* rk     = (const float*)d_in[2];
    const float* ik     = (const float*)d_in[3];
    const float* rrk    = (const float*)d_in[4];
    const float* irk    = (const float*)d_in[5];
    const float* rb     = (const float*)d_in[6];
    const float* ib     = (const float*)d_in[7];
    float* out = (float*)d_out;

    float *PreR, *PreI, *XhR, *XhI, *HhR, *HhI, *K1p, *K1x, *K1h;
    __half *Wr, *Rr, *Wnn, *Rnn, *Wdd, *Rdd;
    __half *X1, *X2, *XS, *H1, *H2, *HS, *R1, *R2, *RS;
    cudaGetSymbolAddress((void**)&PreR, g_PreR);
    cudaGetSymbolAddress((void**)&PreI, g_PreI);
    cudaGetSymbolAddress((void**)&XhR,  g_XhR);
    cudaGetSymbolAddress((void**)&XhI,  g_XhI);
    cudaGetSymbolAddress((void**)&HhR,  g_HhR);
    cudaGetSymbolAddress((void**)&HhI,  g_HhI);
    cudaGetSymbolAddress((void**)&K1p,  g_K1p);
    cudaGetSymbolAddress((void**)&K1x,  g_K1x);
    cudaGetSymbolAddress((void**)&K1h,  g_K1h);
    cudaGetSymbolAddress((void**)&Wr,   g_Wr);
    cudaGetSymbolAddress((void**)&Rr,   g_Rr);
    cudaGetSymbolAddress((void**)&Wnn,  g_Wnn);
    cudaGetSymbolAddress((void**)&Rnn,  g_Rnn);
    cudaGetSymbolAddress((void**)&Wdd,  g_Wdd);
    cudaGetSymbolAddress((void**)&Rdd,  g_Rdd);
    cudaGetSymbolAddress((void**)&X1,   g_X1);
    cudaGetSymbolAddress((void**)&X2,   g_X2);
    cudaGetSymbolAddress((void**)&XS,   g_XS);
    cudaGetSymbolAddress((void**)&H1,   g_H1);
    cudaGetSymbolAddress((void**)&H2,   g_H2);
    cudaGetSymbolAddress((void**)&HS,   g_HS);
    cudaGetSymbolAddress((void**)&R1,   g_R1);
    cudaGetSymbolAddress((void**)&R2,   g_R2);
    cudaGetSymbolAddress((void**)&RS,   g_RS);

    cudaFuncSetAttribute(gemm_g, cudaFuncAttributeMaxDynamicSharedMemorySize, SMEM_TOTAL);

    // prep
    k_wprep<<<12288, 256>>>((const float4*)rk, (const float4*)ik,
                            (const float4*)rrk, (const float4*)irk,
                            (uint2*)Wr, (uint2*)Rr, (uint2*)Wnn,
                            (uint2*)Rnn, (uint2*)Wdd, (uint2*)Rdd);
    k_acts<<<dim3(2048, 2), 256>>>(inputs, h, X1, X2, XS, H1, H2, HS);

    // L1: k1 GEMMs.  Pre-k1: (XS@Wr + HS@Rr) cols 0..4095 -> K1p
    //                Xh-k1:  XS@Wr cols 4096..6143 -> K1x
    GP preK1{XS, HS, Wr, Rr, nullptr, nullptr, K1p, 0,    2, 4096, 1.f};
    GP xhK1 {XS, XS, Wr, Wr, nullptr, nullptr, K1x, 4096, 1, 2048, 1.f};
    gemm_g<<<dim3(8, 48), 256, SMEM_TOTAL>>>(preK1, xhK1, xhK1, xhK1, 32, 48, 48);

    // L2: k2/k3 + combine.
    GP preI{X1, H1, Wnn, Rnn, K1p, ib,        PreI, 0,    2, 4096,  1.f};
    GP preR{X2, H2, Wdd, Rdd, K1p, rb,        PreR, 0,    2, 4096, -1.f};
    GP xhI {X1, X1, Wnn, Wnn, K1x, ib + 4096, XhI,  4096, 1, 2048,  1.f};
    GP xhR {X2, X2, Wdd, Wdd, K1x, rb + 4096, XhR,  4096, 1, 2048, -1.f};
    gemm_g<<<dim3(8, 96), 256, SMEM_TOTAL>>>(preI, preR, xhI, xhR, 32, 64, 80);

    // rh halves + sum
    k_rh<<<2048, 256>>>(h, PreR, PreI, R1, R2, RS);

    // L3: Hh-k1 = RS@Rr cols 4096.. -> K1h
    GP hhK1{RS, RS, Rr, Rr, nullptr, nullptr, K1h, 4096, 1, 2048, 1.f};
    gemm_g<<<dim3(8, 16), 256, SMEM_TOTAL>>>(hhK1, hhK1, hhK1, hhK1, 16, 16, 16);

    // L4: HhI = K1h + R1@Rnn ; HhR = K1h - R2@Rdd
    GP hhI{R1, R1, Rnn, Rnn, K1h, nullptr, HhI, 4096, 1, 2048,  1.f};
    GP hhR{R2, R2, Rdd, Rdd, K1h, nullptr, HhR, 4096, 1, 2048, -1.f};
    gemm_g<<<dim3(8, 32), 256, SMEM_TOTAL>>>(hhI, hhR, hhR, hhR, 16, 32, 32);

    // combine
    k_final<<<4096, 256>>>(h, PreR, PreI, XhR, XhI, HhR, HhI, out);
}

// round 11
// speedup vs baseline: 3.2164x; 1.1114x over previous
#include <cuda_runtime.h>
#include <cuda_fp16.h>
#include <cstdint>

// ---------------- scratch (device globals) ----------------
__device__ float g_K1p[1024 * 4096];
__device__ float g_K2p[1024 * 4096];
__device__ float g_K3p[1024 * 4096];
__device__ float g_K1x[1024 * 2048];
__device__ float g_K2x[1024 * 2048];
__device__ float g_K3x[1024 * 2048];
__device__ float g_K1h[1024 * 2048];
__device__ float g_K2h[1024 * 2048];
__device__ float g_K3h[1024 * 2048];
// weights fp16: plain, -(W+Wi), (W-Wi) for kernel + recurrent
__device__ __half g_Wr [2048 * 6144];
__device__ __half g_Rr [2048 * 6144];
__device__ __half g_Wnn[2048 * 6144];
__device__ __half g_Rnn[2048 * 6144];
__device__ __half g_Wdd[2048 * 6144];
__device__ __half g_Rdd[2048 * 6144];
// activations fp16: halves + sums (compact [1024 x 2048])
__device__ __half g_X1[1024 * 2048];
__device__ __half g_X2[1024 * 2048];
__device__ __half g_XS[1024 * 2048];
__device__ __half g_H1[1024 * 2048];
__device__ __half g_H2[1024 * 2048];
__device__ __half g_HS[1024 * 2048];
__device__ __half g_R1[1024 * 2048];
__device__ __half g_R2[1024 * 2048];
__device__ __half g_RS[1024 * 2048];

__device__ __forceinline__ uint32_t s2u(const void* p) {
    uint32_t a;
    asm("{ .reg .u64 t; cvta.to.shared.u64 t, %1; cvt.u32.u64 %0, t; }" : "=r"(a) : "l"(p));
    return a;
}

#define CP_ASYNC16(dst, src) \
    asm volatile("cp.async.cg.shared.global [%0], [%1], 16;" :: "r"(dst), "l"(src))
#define CP_COMMIT() asm volatile("cp.async.commit_group;" ::: "memory")
#define CP_WAIT1()  asm volatile("cp.async.wait_group 1;" ::: "memory")
#define CP_WAIT0()  asm volatile("cp.async.wait_group 0;" ::: "memory")

#define SW(o) ((o) ^ (((o) >> 3) & 0x70))

#define LDSM4(r, a) \
    asm volatile("ldmatrix.sync.aligned.m8n8.x4.shared.b16 {%0,%1,%2,%3}, [%4];" \
        : "=r"((r)[0]), "=r"((r)[1]), "=r"((r)[2]), "=r"((r)[3]) : "r"(a))
#define LDSMT4(r, a) \
    asm volatile("ldmatrix.sync.aligned.m8n8.x4.trans.shared.b16 {%0,%1,%2,%3}, [%4];" \
        : "=r"((r)[0]), "=r"((r)[1]), "=r"((r)[2]), "=r"((r)[3]) : "r"(a))

#define MMA16(acc, a, b0, b1) \
    asm volatile("mma.sync.aligned.m16n8k16.row.col.f32.f16.f16.f32 " \
        "{%0,%1,%2,%3},{%4,%5,%6,%7},{%8,%9},{%0,%1,%2,%3};" \
        : "+f"((acc)[0]), "+f"((acc)[1]), "+f"((acc)[2]), "+f"((acc)[3]) \
        : "r"((a)[0]), "r"((a)[1]), "r"((a)[2]), "r"((a)[3]), "r"(b0), "r"(b1))

#define STAGE      32768
#define SM_B_OFF   16384
#define NSTAGE     3
#define SMEM_TOTAL (NSTAGE * STAGE)

// problem descriptor: C = sgn*(sum_seg A_s @ B_s[wcol..]) + bias
struct GP {
    const __half *A0, *A1;     // per-2048-K-segment activation [1024 x 2048]
    const __half *B0, *B1;     // per-segment weight [2048 x 6144]
    const float  *bias;        // optional bias[col]
    float        *C;
    int wcol, nseg, ldC;
    float sgn;
};
struct GP6 {
    GP  p[6];
    int yb[5];                 // cumulative y bounds (ranges [0,yb0),[yb0,yb1),...)
};

// ---------------------------------------------------------------------------
// generic fp16 GEMM, fp32 accum; up to 6 problems per launch selected by
// blockIdx.y ranges. 256 thr, 8 warps, CTA 128x128, warp 64x32, 3-stage
// cp.async pipeline, double-buffered A fragments, 2 CTAs/SM.
// ---------------------------------------------------------------------------
__global__ void __launch_bounds__(256, 2) gemm_g(GP6 P)
{
    extern __shared__ char smem[];
    const uint32_t sb = s2u(smem);

    const int tid  = threadIdx.x;
    const int lane = tid & 31;
    const int warp = tid >> 5;
    const int wm   = warp >> 2;
    const int wn   = warp & 3;
    const int bm   = blockIdx.x;
    const int by   = blockIdx.y;

    int idx = 0;
    #pragma unroll
    for (int q = 0; q < 5; q++)
        if (by >= P.yb[q]) idx = q + 1;
    const int bn = by - (idx ? P.yb[idx - 1] : 0);

    const __half* A0 = P.p[idx].A0;
    const __half* A1 = P.p[idx].A1;
    const __half* B0 = P.p[idx].B0;
    const __half* B1 = P.p[idx].B1;
    const int wcol = P.p[idx].wcol;
    const int nseg = P.p[idx].nseg;
    const int KT = nseg << 5;

    float acc[4][4][4];
    #pragma unroll
    for (int i = 0; i < 4; i++)
        #pragma unroll
        for (int j = 0; j < 4; j++)
            #pragma unroll
            for (int k = 0; k < 4; k++) acc[i][j][k] = 0.f;

    const int arow = tid >> 1;
    const int ac0  = (tid & 1) * 4;
    const int brow = tid >> 2;
    const int bc0  = (tid & 3) * 4;
    const size_t mBase = (size_t)(bm * 128);
    const int    gn    = wcol + bn * 128;

    const uint32_t xorv = (lane & 7) << 4;
    const uint32_t l87  = (lane & 7) + ((lane >> 3) & 1) * 8;
    const uint32_t aRowOff = (wm * 64 + l87) * 128;
    const uint32_t bRowOff = SM_B_OFF + (wn >> 1) * 8192 +
                             ((lane >> 3) * 8 + (lane & 7)) * 128;
    const uint32_t p16c = (lane >> 4) * 16;
    const uint32_t bsel = (wn & 1) * 64;

#define CP_STAGE(KT_IDX)                                                            \
    do {                                                                            \
        const int kg = (KT_IDX) * 64;                                               \
        const int klocal = kg & 2047;                                               \
        const uint32_t sbase = sb + ((KT_IDX) % NSTAGE) * STAGE;                    \
        const __half* Ap = (kg >= 2048) ? A1 : A0;                                  \
        const __half* asrc = Ap + (mBase + arow) * 2048 + klocal + ac0 * 8;         \
        _Pragma("unroll")                                                           \
        for (int i = 0; i < 4; i++)                                                 \
            CP_ASYNC16(sbase + SW(arow * 128 + (ac0 + i) * 16), asrc + i * 8);      \
        const __half* Bp = (kg >= 2048) ? B1 : B0;                                  \
        const __half* bsrc = Bp + (size_t)(klocal + brow) * 6144 + gn;              \
        _Pragma("unroll")                                                           \
        for (int i = 0; i < 4; i++) {                                               \
            const int ch = bc0 + i, pp = ch >> 3, cc = ch & 7;                      \
            CP_ASYNC16(sbase + SM_B_OFF + pp * 8192 + SW(brow * 128 + cc * 16),     \
                       bsrc + pp * 64 + cc * 8);                                    \
        }                                                                           \
        CP_COMMIT();                                                                \
    } while (0)

#define LDA(dst, BASE, S)                                                           \
    do {                                                                            \
        const uint32_t off = ((uint32_t)((S) * 32) + p16c) ^ xorv;                  \
        _Pragma("unroll")                                                           \
        for (int mf = 0; mf < 4; mf++)                                              \
            LDSM4((dst)[mf], (BASE) + aRowOff + mf * 2048 + off);                   \
    } while (0)

#define LDB(dst, BASE, KH)                                                          \
    do {                                                                            \
        _Pragma("unroll")                                                           \
        for (int nf = 0; nf < 4; nf++)                                              \
            LDSMT4((dst)[nf], (BASE) + bRowOff + (KH) * 4096 +                      \
                   (((uint32_t)(bsel + nf * 16)) ^ xorv));                          \
    } while (0)

    uint32_t afr[2][4][4];
    uint32_t bfr[4][4];

    CP_STAGE(0);
    CP_STAGE(1);
    CP_WAIT1();
    __syncthreads();

    for (int kt = 0; kt < KT; ++kt) {
        const uint32_t base = sb + (kt % NSTAGE) * STAGE;

        LDA(afr[0], base, 0);
        if (kt + 2 < KT) CP_STAGE(kt + 2);

        #pragma unroll
        for (int s = 0; s < 4; s++) {
            if ((s & 1) == 0) LDB(bfr, base, s >> 1);
            if (s < 3) LDA(afr[(s + 1) & 1], base, s + 1);
            const int sh = s & 1;
            #pragma unroll
            for (int mf = 0; mf < 4; mf++)
                #pragma unroll
                for (int nf = 0; nf < 4; nf++)
                    MMA16(acc[mf][nf], afr[s & 1][mf],
                          bfr[nf][sh * 2], bfr[nf][sh * 2 + 1]);
        }

        if (kt + 1 < KT) {
            if (kt + 2 < KT) CP_WAIT1(); else CP_WAIT0();
            __syncthreads();
        }
    }

    // epilogue: C = sgn*acc + bias
    const float* bias = P.p[idx].bias;
    float*       C    = P.p[idx].C;
    const int    ldC  = P.p[idx].ldC;
    const float  sg   = P.p[idx].sgn;

    const int gid = lane >> 2;
    const int tig = lane & 3;
    #pragma unroll
    for (int mf = 0; mf < 4; mf++) {
        const int row = bm * 128 + wm * 64 + mf * 16 + gid;
        #pragma unroll
        for (int nf = 0; nf < 4; nf++) {
            const int col = bn * 128 + wn * 32 + nf * 8 + tig * 2;
            float b0 = 0.f, b1 = 0.f;
            if (bias) { b0 = bias[col]; b1 = bias[col + 1]; }
            float2 v0 = make_float2(sg * acc[mf][nf][0] + b0, sg * acc[mf][nf][1] + b1);
            float2 v1 = make_float2(sg * acc[mf][nf][2] + b0, sg * acc[mf][nf][3] + b1);
            *(float2*)(C + (size_t)row       * ldC + col) = v0;
            *(float2*)(C + (size_t)(row + 8) * ldC + col) = v1;
        }
    }
#undef CP_STAGE
#undef LDA
#undef LDB
}

// ---------------- elementwise ----------------
__device__ __forceinline__ float hsig(float x) {
    return fminf(fmaxf(fmaf(0.2f, x, 0.5f), 0.f), 1.f);
}
__device__ __forceinline__ uint2 pack4(float a, float b, float c, float d) {
    __half2 lo = __floats2half2_rn(a, b);
    __half2 hi = __floats2half2_rn(c, d);
    uint2 o;
    o.x = *(uint32_t*)&lo;
    o.y = *(uint32_t*)&hi;
    return o;
}

// weight prep (read-once)
__global__ void k_wprep(const float4* __restrict__ rk,  const float4* __restrict__ ik,
                        const float4* __restrict__ rrk, const float4* __restrict__ irk,
                        uint2* __restrict__ Wr,  uint2* __restrict__ Rr,
                        uint2* __restrict__ Wnn, uint2* __restrict__ Rnn,
                        uint2* __restrict__ Wdd, uint2* __restrict__ Rdd)
{
    int i = blockIdx.x * blockDim.x + threadIdx.x;
    float4 a = rk[i], b = ik[i];
    Wr[i]  = pack4(a.x, a.y, a.z, a.w);
    Wnn[i] = pack4(-(a.x + b.x), -(a.y + b.y), -(a.z + b.z), -(a.w + b.w));
    Wdd[i] = pack4(a.x - b.x, a.y - b.y, a.z - b.z, a.w - b.w);
    float4 c = rrk[i], d = irk[i];
    Rr[i]  = pack4(c.x, c.y, c.z, c.w);
    Rnn[i] = pack4(-(c.x + d.x), -(c.y + d.y), -(c.z + d.z), -(c.w + d.w));
    Rdd[i] = pack4(c.x - d.x, c.y - d.y, c.z - d.z, c.w - d.w);
}

// activations -> halves + sum (fp16, compact stride 2048); y=0: inputs, y=1: h
__global__ void k_acts(const float* __restrict__ x, const float* __restrict__ h,
                       __half* __restrict__ X1, __half* __restrict__ X2, __half* __restrict__ XS,
                       __half* __restrict__ H1, __half* __restrict__ H2, __half* __restrict__ HS)
{
    const float* in = blockIdx.y ? h : x;
    __half *o1 = blockIdx.y ? H1 : X1, *o2 = blockIdx.y ? H2 : X2, *os = blockIdx.y ? HS : XS;
    int i4 = blockIdx.x * blockDim.x + threadIdx.x;
    int idx = i4 * 4;
    int m = idx >> 11, j = idx & 2047;
    float4 v1 = *(const float4*)(in + (size_t)m * 4096 + j);
    float4 v2 = *(const float4*)(in + (size_t)m * 4096 + 2048 + j);
    *(uint2*)(o1 + idx) = pack4(v1.x, v1.y, v1.z, v1.w);
    *(uint2*)(o2 + idx) = pack4(v2.x, v2.y, v2.z, v2.w);
    *(uint2*)(os + idx) = pack4(v1.x + v2.x, v1.y + v2.y, v1.z + v2.z, v1.w + v2.w);
}

// rh halves + sum. r gate: rR = hsig(K1p + K3p)[cols 2048..4095] (K3p has -k3+rb),
//                          rI = hsig(K1p + K2p)[cols 2048..4095] (K2p has +k2+ib)
__global__ void k_rh(const float* __restrict__ h,
                     const float* __restrict__ K1p, const float* __restrict__ K2p,
                     const float* __restrict__ K3p,
                     __half* __restrict__ R1, __half* __restrict__ R2, __half* __restrict__ RS)
{
    int i4 = blockIdx.x * blockDim.x + threadIdx.x;
    int idx = i4 * 4;
    int m = idx >> 11, j = idx & 2047;
    size_t o = (size_t)m * 4096 + 2048 + j;
    float4 k1 = *(const float4*)(K1p + o);
    float4 k2 = *(const float4*)(K2p + o);
    float4 k3 = *(const float4*)(K3p + o);
    float4 h1 = *(const float4*)(h + (size_t)m * 4096 + j);
    float4 h2 = *(const float4*)(h + (size_t)m * 4096 + 2048 + j);
    float a1 = hsig(k1.x + k3.x) * h1.x, b1 = hsig(k1.y + k3.y) * h1.y,
          c1 = hsig(k1.z + k3.z) * h1.z, d1 = hsig(k1.w + k3.w) * h1.w;
    float a2 = hsig(k1.x + k2.x) * h2.x, b2 = hsig(k1.y + k2.y) * h2.y,
          c2 = hsig(k1.z + k2.z) * h2.z, d2 = hsig(k1.w + k2.w) * h2.w;
    *(uint2*)(R1 + idx) = pack4(a1, b1, c1, d1);
    *(uint2*)(R2 + idx) = pack4(a2, b2, c2, d2);
    *(uint2*)(RS + idx) = pack4(a1 + a2, b1 + b2, c1 + c2, d1 + d2);
}

// h_out = z*h + (1-z)*tanh(Xh + Hh); z gate = cols 0..2047 of Pre.
// real (j<2048):  z = hsig(K1p+K3p), hh = tanh(K1x+K3x + K1h+K3h)
// imag:           z = hsig(K1p+K2p), hh = tanh(K1x+K2x + K1h+K2h)
__global__ void k_final(const float* __restrict__ h,
                        const float* __restrict__ K1p, const float* __restrict__ K2p,
                        const float* __restrict__ K3p,
                        const float* __restrict__ K1x, const float* __restrict__ K2x,
                        const float* __restrict__ K3x,
                        const float* __restrict__ K1h, const float* __restrict__ K2h,
                        const float* __restrict__ K3h,
                        float* __restrict__ out)
{
    int i4 = blockIdx.x * blockDim.x + threadIdx.x;
    int idx = i4 * 4;
    int m  = idx >> 12;
    int j  = idx & 4095;
    int jj = j & 2047;
    size_t op = (size_t)m * 4096 + jj;
    size_t oc = (size_t)m * 2048 + jj;
    float4 k1 = *(const float4*)(K1p + op);
    float4 x1 = *(const float4*)(K1x + oc);
    float4 h1 = *(const float4*)(K1h + oc);
    float4 kv, xv, hv2;
    if (j < 2048) {
        kv  = *(const float4*)(K3p + op);
        xv  = *(const float4*)(K3x + oc);
        hv2 = *(const float4*)(K3h + oc);
    } else {
        kv  = *(const float4*)(K2p + op);
        xv  = *(const float4*)(K2x + oc);
        hv2 = *(const float4*)(K2h + oc);
    }
    float4 hv = *(const float4*)(h + idx);
    float4 o;
    float z, t;
    z = hsig(k1.x + kv.x); t = tanhf(x1.x + xv.x + h1.x + hv2.x); o.x = z * hv.x + (1.f - z) * t;
    z = hsig(k1.y + kv.y); t = tanhf(x1.y + xv.y + h1.y + hv2.y); o.y = z * hv.y + (1.f - z) * t;
    z = hsig(k1.z + kv.z); t = tanhf(x1.z + xv.z + h1.z + hv2.z); o.z = z * hv.z + (1.f - z) * t;
    z = hsig(k1.w + kv.w); t = tanhf(x1.w + xv.w + h1.w + hv2.w); o.w = z * hv.w + (1.f - z) * t;
    *(float4*)(out + idx) = o;
}

// ---------------- launch ----------------
extern "C" void kernel_launch(void* const* d_in, const int* in_sizes, int n_in,
                              void* d_out, int out_size)
{
    const float* inputs = (const float*)d_in[0];
    const float* h      = (const float*)d_in[1];
    const float* rk     = (const float*)d_in[2];
    const float* ik     = (const float*)d_in[3];
    const float* rrk    = (const float*)d_in[4];
    const float* irk    = (const float*)d_in[5];
    const float* rb     = (const float*)d_in[6];
    const float* ib     = (const float*)d_in[7];
    float* out = (float*)d_out;

    float *K1p, *K2p, *K3p, *K1x, *K2x, *K3x, *K1h, *K2h, *K3h;
    __half *Wr, *Rr, *Wnn, *Rnn, *Wdd, *Rdd;
    __half *X1, *X2, *XS, *H1, *H2, *HS, *R1, *R2, *RS;
    cudaGetSymbolAddress((void**)&K1p, g_K1p);
    cudaGetSymbolAddress((void**)&K2p, g_K2p);
    cudaGetSymbolAddress((void**)&K3p, g_K3p);
    cudaGetSymbolAddress((void**)&K1x, g_K1x);
    cudaGetSymbolAddress((void**)&K2x, g_K2x);
    cudaGetSymbolAddress((void**)&K3x, g_K3x);
    cudaGetSymbolAddress((void**)&K1h, g_K1h);
    cudaGetSymbolAddress((void**)&K2h, g_K2h);
    cudaGetSymbolAddress((void**)&K3h, g_K3h);
    cudaGetSymbolAddress((void**)&Wr,  g_Wr);
    cudaGetSymbolAddress((void**)&Rr,  g_Rr);
    cudaGetSymbolAddress((void**)&Wnn, g_Wnn);
    cudaGetSymbolAddress((void**)&Rnn, g_Rnn);
    cudaGetSymbolAddress((void**)&Wdd, g_Wdd);
    cudaGetSymbolAddress((void**)&Rdd, g_Rdd);
    cudaGetSymbolAddress((void**)&X1,  g_X1);
    cudaGetSymbolAddress((void**)&X2,  g_X2);
    cudaGetSymbolAddress((void**)&XS,  g_XS);
    cudaGetSymbolAddress((void**)&H1,  g_H1);
    cudaGetSymbolAddress((void**)&H2,  g_H2);
    cudaGetSymbolAddress((void**)&HS,  g_HS);
    cudaGetSymbolAddress((void**)&R1,  g_R1);
    cudaGetSymbolAddress((void**)&R2,  g_R2);
    cudaGetSymbolAddress((void**)&RS,  g_RS);

    cudaFuncSetAttribute(gemm_g, cudaFuncAttributeMaxDynamicSharedMemorySize, SMEM_TOTAL);

    // prep
    k_wprep<<<12288, 256>>>((const float4*)rk, (const float4*)ik,
                            (const float4*)rrk, (const float4*)irk,
                            (uint2*)Wr, (uint2*)Rr, (uint2*)Wnn,
                            (uint2*)Rnn, (uint2*)Wdd, (uint2*)Rdd);
    k_acts<<<dim3(2048, 2), 256>>>(inputs, h, X1, X2, XS, H1, H2, HS);

    // G1: all x/h GEMMs in ONE launch (6 problems, long-K first).
    //  K1p = XS@Wr + HS@Rr          (cols 0..4095)
    //  K2p = X1@Wnn + H1@Rnn + ib   (cols 0..4095)
    //  K3p = -(X2@Wdd + H2@Rdd) + rb
    //  K1x = XS@Wr                  (cols 4096..6143)
    //  K2x = X1@Wnn + ib[4096..]
    //  K3x = -(X2@Wdd) + rb[4096..]
    {
        GP6 P;
        P.p[0] = {XS, HS, Wr,  Rr,  nullptr,    K1p, 0,    2, 4096,  1.f};
        P.p[1] = {X1, H1, Wnn, Rnn, ib,         K2p, 0,    2, 4096,  1.f};
        P.p[2] = {X2, H2, Wdd, Rdd, rb,         K3p, 0,    2, 4096, -1.f};
        P.p[3] = {XS, XS, Wr,  Wr,  nullptr,    K1x, 4096, 1, 2048,  1.f};
        P.p[4] = {X1, X1, Wnn, Wnn, ib + 4096,  K2x, 4096, 1, 2048,  1.f};
        P.p[5] = {X2, X2, Wdd, Wdd, rb + 4096,  K3x, 4096, 1, 2048, -1.f};
        P.yb[0] = 32; P.yb[1] = 64; P.yb[2] = 96; P.yb[3] = 112; P.yb[4] = 128;
        gemm_g<<<dim3(8, 144), 256, SMEM_TOTAL>>>(P);
    }

    // rh halves + sum (combines Gauss terms for the r gate on the fly)
    k_rh<<<2048, 256>>>(h, K1p, K2p, K3p, R1, R2, RS);

    // G2: all Hh GEMMs in ONE launch (3 problems).
    //  K1h = RS@Rr ; K2h = R1@Rnn ; K3h = -(R2@Rdd)    (cols 4096..6143)
    {
        GP6 P;
        P.p[0] = {RS, RS, Rr,  Rr,  nullptr, K1h, 4096, 1, 2048,  1.f};
        P.p[1] = {R1, R1, Rnn, Rnn, nullptr, K2h, 4096, 1, 2048,  1.f};
        P.p[2] = {R2, R2, Rdd, Rdd, nullptr, K3h, 4096, 1, 2048, -1.f};
        P.p[3] = P.p[2]; P.p[4] = P.p[2]; P.p[5] = P.p[2];
        P.yb[0] = 16; P.yb[1] = 32; P.yb[2] = 48; P.yb[3] = 48; P.yb[4] = 48;
        gemm_g<<<dim3(8, 48), 256, SMEM_TOTAL>>>(P);
    }

    // combine
    k_final<<<4096, 256>>>(h, K1p, K2p, K3p, K1x, K2x, K3x, K1h, K2h, K3h, out);
}